// round 3
// baseline (speedup 1.0000x reference)
#include <cuda_runtime.h>
#include <cuda_bf16.h>

// ---------------- problem constants ----------------
#define B 8
#define H 16
#define DIM 2048
#define QLR 1536
#define KVLR 512
#define DN 128
#define DR 64
#define DV 128
#define T_TOT 8192
#define T_PREFIX 8191
#define NCHUNK 32
#define CHUNK 256          // tokens per CTA in attention
#define TB 16              // tokens per inner block
#define DHEAD 576          // 512 + 64
#define SCALEF 0.07216878364870322f   // (DN+DR)^-0.5 = 192^-0.5

// ---------------- device scratch (no allocations allowed) ----------------
__device__ float g_qa  [B*QLR];
__device__ float g_kvpe[B*(KVLR+DR)];
__device__ float g_qan [B*QLR];
__device__ float g_kvn [B*KVLR];
__device__ float g_pen [B*DR];
__device__ float g_q   [B*H*(DN+DR)];        // 8*3072
__device__ float g_qfull[B*H*DHEAD];         // 8*16*576
__device__ float g_pm  [B*NCHUNK*H];
__device__ float g_pl  [B*NCHUNK*H];
__device__ float g_pout[B*NCHUNK*H*KVLR];    // 8.4 MB
__device__ float g_out2[B*H*DV];             // 16384

__device__ __forceinline__ float dot4(float4 a, float4 b){
    return a.x*b.x + a.y*b.y + a.z*b.z + a.w*b.w;
}

// ========== K1: qa = x @ wq_a^T + b ; kvpe = x @ wkv_a^T + b ==========
// weights read ONCE; all 8 batches looped per warp (x staged in smem).
__global__ void k_proj_a(const float* __restrict__ x,
                         const float* __restrict__ wqa, const float* __restrict__ bqa,
                         const float* __restrict__ wkva, const float* __restrict__ bkva){
    extern __shared__ float xs[];               // 8*2048 floats = 64 KB
    int tid = threadIdx.x;
    for (int i = tid; i < B*DIM; i += blockDim.x) xs[i] = x[i];
    __syncthreads();
    int warp = tid >> 5, lane = tid & 31;
    int r = blockIdx.x * 8 + warp;              // 0..2111
    if (r >= QLR + KVLR + DR) return;
    const float* wrow; float bias;
    if (r < QLR) { wrow = wqa + (long)r*DIM; bias = bqa[r]; }
    else         { wrow = wkva + (long)(r-QLR)*DIM; bias = bkva[r-QLR]; }
    float w[64];
    #pragma unroll
    for (int k = 0; k < 64; k++) w[k] = wrow[lane + 32*k];
    for (int b = 0; b < B; b++){
        const float* xb = xs + b*DIM;
        float s = 0.f;
        #pragma unroll
        for (int k = 0; k < 64; k++) s += w[k]*xb[lane + 32*k];
        #pragma unroll
        for (int o = 16; o; o >>= 1) s += __shfl_xor_sync(0xffffffffu, s, o);
        if (lane == 0){
            if (r < QLR) g_qa[b*QLR + r] = s + bias;
            else         g_kvpe[b*(KVLR+DR) + (r-QLR)] = s + bias;
        }
    }
}

// ========== K2: RMS-norm qa and kv; rope k_pe ==========
__global__ void k_norm_rope(const float* __restrict__ qnw, const float* __restrict__ kvnw,
                            const float* __restrict__ fcos, const float* __restrict__ fsin){
    int b = blockIdx.x, tid = threadIdx.x;      // 512 threads
    __shared__ float red[16];
    __shared__ float sq, skv;
    float s = 0.f;
    for (int i = tid; i < QLR; i += 512){ float v = g_qa[b*QLR+i]; s += v*v; }
    #pragma unroll
    for (int o = 16; o; o >>= 1) s += __shfl_xor_sync(0xffffffffu, s, o);
    if ((tid&31) == 0) red[tid>>5] = s;
    __syncthreads();
    if (tid == 0){ float t=0; for (int i=0;i<16;i++) t += red[i];
                   sq = rsqrtf(t*(1.f/QLR) + 1e-6f); }
    __syncthreads();
    float s2 = 0.f;
    { float v = (tid < KVLR) ? g_kvpe[b*(KVLR+DR)+tid] : 0.f; s2 = v*v; }
    #pragma unroll
    for (int o = 16; o; o >>= 1) s2 += __shfl_xor_sync(0xffffffffu, s2, o);
    if ((tid&31) == 0) red[tid>>5] = s2;
    __syncthreads();
    if (tid == 0){ float t=0; for (int i=0;i<16;i++) t += red[i];
                   skv = rsqrtf(t*(1.f/KVLR) + 1e-6f); }
    __syncthreads();
    for (int i = tid; i < QLR; i += 512) g_qan[b*QLR+i] = g_qa[b*QLR+i]*qnw[i]*sq;
    if (tid < KVLR) g_kvn[b*KVLR+tid] = g_kvpe[b*(KVLR+DR)+tid]*kvnw[tid]*skv;
    if (tid < DR){
        int i = tid >> 1;
        float xr = g_kvpe[b*(KVLR+DR)+KVLR+2*i];
        float xi = g_kvpe[b*(KVLR+DR)+KVLR+2*i+1];
        float c = fcos[i], sn = fsin[i];
        g_pen[b*DR+tid] = (tid&1) ? (xr*sn + xi*c) : (xr*c - xi*sn);
    }
}

// ========== K3: q = qa_n @ wq_b^T + b ==========
__global__ void k_proj_qb(const float* __restrict__ wqb, const float* __restrict__ bqb){
    extern __shared__ float qs[];               // 8*1536 floats = 48 KB
    int tid = threadIdx.x;
    for (int i = tid; i < B*QLR; i += blockDim.x) qs[i] = g_qan[i];
    __syncthreads();
    int warp = tid >> 5, lane = tid & 31;
    int r = blockIdx.x * 8 + warp;              // 0..3071
    const float* wr = wqb + (long)r*QLR;
    float w[48];
    #pragma unroll
    for (int k = 0; k < 48; k++) w[k] = wr[lane + 32*k];
    float bias = bqb[r];
    for (int b = 0; b < B; b++){
        const float* xb = qs + b*QLR;
        float s = 0.f;
        #pragma unroll
        for (int k = 0; k < 48; k++) s += w[k]*xb[lane + 32*k];
        #pragma unroll
        for (int o = 16; o; o >>= 1) s += __shfl_xor_sync(0xffffffffu, s, o);
        if (lane == 0) g_q[b*(H*(DN+DR)) + r] = s + bias;
    }
}

// ========== K4: q_full = [q_nope @ wkv_b[:, :DN] (512) , rope(q_pe) (64)] ==========
__global__ void k_qfull(const float* __restrict__ wkvb,
                        const float* __restrict__ fcos, const float* __restrict__ fsin){
    int h = blockIdx.x, part = blockIdx.y, tid = threadIdx.x;  // 128 threads
    if (part < 4){
        __shared__ float qn[B][DN];
        for (int i = tid; i < B*DN; i += 128){ int b = i>>7, d = i&127;
            qn[b][d] = g_q[b*(H*(DN+DR)) + h*(DN+DR) + d]; }
        __syncthreads();
        int c = part*128 + tid;
        float acc[B];
        #pragma unroll
        for (int b = 0; b < B; b++) acc[b] = 0.f;
        for (int d = 0; d < DN; d++){
            float w = wkvb[(long)(h*(DN+DV) + d)*KVLR + c];
            #pragma unroll
            for (int b = 0; b < B; b++) acc[b] += qn[b][d]*w;
        }
        #pragma unroll
        for (int b = 0; b < B; b++) g_qfull[(b*H + h)*DHEAD + c] = acc[b];
    } else {
        if (tid < DR){
            int i = tid >> 1;
            float c = fcos[i], sn = fsin[i];
            for (int b = 0; b < B; b++){
                float xr = g_q[b*(H*(DN+DR)) + h*(DN+DR) + DN + 2*i];
                float xi = g_q[b*(H*(DN+DR)) + h*(DN+DR) + DN + 2*i + 1];
                g_qfull[(b*H + h)*DHEAD + KVLR + tid] =
                    (tid&1) ? (xr*sn + xi*c) : (xr*c - xi*sn);
            }
        }
    }
}

// ========== K5: flash attention, split over 32 chunks of 256 tokens ==========
// grid (32, 8), 512 threads. All 16 heads processed per CTA so kv is read once.
__global__ void k_attn(const float* __restrict__ kvp, const float* __restrict__ pep){
    extern __shared__ float sm[];
    float* q_s = sm;                      // 16*576
    float* kvb = sm + H*DHEAD;            // 16*576
    float* p_s = sm + 2*H*DHEAD;          // 16*16 scores -> probs
    float* s_m = sm + 2*H*DHEAD + 256;    // 16
    float* s_l = s_m + 16;                // 16
    float* s_c = s_l + 16;                // 16
    int chunk = blockIdx.x, b = blockIdx.y, tid = threadIdx.x;
    int warp = tid >> 5, lane = tid & 31;

    for (int i = tid; i < H*DHEAD; i += 512) q_s[i] = g_qfull[b*H*DHEAD + i];
    if (tid < H){ s_m[tid] = -1e30f; s_l[tid] = 0.f; }
    float acc[H];
    #pragma unroll
    for (int h = 0; h < H; h++) acc[h] = 0.f;

    for (int blk = 0; blk < CHUNK/TB; blk++){
        __syncthreads();
        int t0 = chunk*CHUNK + blk*TB;
        // load kv block (16 tokens x 576) into smem; last token comes from new-token buffers
        for (int i = tid; i < TB*KVLR; i += 512){
            int t = i >> 9, c = i & 511; int tg = t0 + t;
            kvb[t*DHEAD + c] = (tg == T_PREFIX) ? g_kvn[b*KVLR + c]
                                                : kvp[((long)b*T_PREFIX + tg)*KVLR + c];
        }
        for (int i = tid; i < TB*DR; i += 512){
            int t = i >> 6, r = i & 63; int tg = t0 + t;
            kvb[t*DHEAD + KVLR + r] = (tg == T_PREFIX) ? g_pen[b*DR + r]
                                                       : pep[((long)b*T_PREFIX + tg)*DR + r];
        }
        __syncthreads();
        // scores: warp <-> token, loop heads, float4 smem reads + shfl reduce
        {
            const float4* K4 = (const float4*)(kvb + warp*DHEAD);
            float4 v0 = K4[lane], v1 = K4[lane+32], v2 = K4[lane+64], v3 = K4[lane+96];
            float4 v4 = (lane < 16) ? K4[128+lane] : make_float4(0.f,0.f,0.f,0.f);
            #pragma unroll
            for (int h = 0; h < H; h++){
                const float4* Q4 = (const float4*)(q_s + h*DHEAD);
                float s = dot4(v0, Q4[lane]) + dot4(v1, Q4[lane+32])
                        + dot4(v2, Q4[lane+64]) + dot4(v3, Q4[lane+96]);
                if (lane < 16) s += dot4(v4, Q4[128+lane]);
                #pragma unroll
                for (int o = 16; o; o >>= 1) s += __shfl_xor_sync(0xffffffffu, s, o);
                if (lane == 0) p_s[h*TB + warp] = s * SCALEF;
            }
        }
        __syncthreads();
        // online softmax bookkeeping (one thread per head)
        if (tid < H){
            int h = tid;
            float bm = -1e30f;
            #pragma unroll
            for (int t = 0; t < TB; t++) bm = fmaxf(bm, p_s[h*TB + t]);
            float mo = s_m[h], mn = fmaxf(mo, bm);
            float corr = __expf(mo - mn);
            float sum = 0.f;
            #pragma unroll
            for (int t = 0; t < TB; t++){
                float p = __expf(p_s[h*TB + t] - mn);
                p_s[h*TB + t] = p; sum += p;
            }
            s_l[h] = s_l[h]*corr + sum; s_m[h] = mn; s_c[h] = corr;
        }
        __syncthreads();
        // accumulate: thread <-> kv column, 16 head accumulators in registers
        {
            int c = tid;
            float kvv[TB];
            #pragma unroll
            for (int t = 0; t < TB; t++) kvv[t] = kvb[t*DHEAD + c];
            #pragma unroll
            for (int h = 0; h < H; h++){
                const float4* P4 = (const float4*)(p_s + h*TB);
                float4 p0 = P4[0], p1 = P4[1], p2 = P4[2], p3 = P4[3];
                float a = acc[h]*s_c[h];
                a += p0.x*kvv[0]  + p0.y*kvv[1]  + p0.z*kvv[2]  + p0.w*kvv[3];
                a += p1.x*kvv[4]  + p1.y*kvv[5]  + p1.z*kvv[6]  + p1.w*kvv[7];
                a += p2.x*kvv[8]  + p2.y*kvv[9]  + p2.z*kvv[10] + p2.w*kvv[11];
                a += p3.x*kvv[12] + p3.y*kvv[13] + p3.z*kvv[14] + p3.w*kvv[15];
                acc[h] = a;
            }
        }
    }
    long base = (long)(b*NCHUNK + chunk)*H*KVLR;
    #pragma unroll
    for (int h = 0; h < H; h++) g_pout[base + h*KVLR + tid] = acc[h];
    if (tid < H){
        g_pm[(b*NCHUNK + chunk)*H + tid] = s_m[tid];
        g_pl[(b*NCHUNK + chunk)*H + tid] = s_l[tid];
    }
}

// ========== K6: combine split-softmax partials + V projection ==========
// grid (16, 8): h = bx, b = by; 512 threads.
__global__ void k_reduce(const float* __restrict__ wkvb){
    int h = blockIdx.x, b = blockIdx.y, tid = threadIdx.x;
    __shared__ float wk[NCHUNK];
    __shared__ float so[KVLR];
    if (tid < NCHUNK){
        float m = g_pm[(b*NCHUNK + tid)*H + h];
        float M = m;
        #pragma unroll
        for (int o = 16; o; o >>= 1) M = fmaxf(M, __shfl_xor_sync(0xffffffffu, M, o));
        float e = __expf(m - M);
        float L = g_pl[(b*NCHUNK + tid)*H + h]*e;
        #pragma unroll
        for (int o = 16; o; o >>= 1) L += __shfl_xor_sync(0xffffffffu, L, o);
        wk[tid] = e / L;
    }
    __syncthreads();
    float out = 0.f;
    for (int k = 0; k < NCHUNK; k++)
        out += wk[k]*g_pout[(long)(b*NCHUNK + k)*H*KVLR + h*KVLR + tid];
    so[tid] = out;
    __syncthreads();
    // out2[d] = sum_c so[c] * wkv_b[h, DN+d, c];   4 threads per d
    int d = tid >> 2, part = tid & 3;
    const float* wr = wkvb + (long)(h*(DN+DV) + DN + d)*KVLR + part*128;
    const float* sp = so + part*128;
    float s = 0.f;
    #pragma unroll 8
    for (int c = 0; c < 128; c++) s += sp[c]*wr[c];
    s += __shfl_xor_sync(0xffffffffu, s, 1);
    s += __shfl_xor_sync(0xffffffffu, s, 2);
    if (part == 0) g_out2[(b*H + h)*DV + d] = s;
}

// ========== K7: y = out2 @ wo^T + wo_b ==========
__global__ void k_proj_o(const float* __restrict__ wo, const float* __restrict__ wob,
                         float* __restrict__ out){
    extern __shared__ float xs[];               // 8*2048 = 64 KB
    int tid = threadIdx.x;
    for (int i = tid; i < B*DIM; i += blockDim.x) xs[i] = g_out2[i];
    __syncthreads();
    int warp = tid >> 5, lane = tid & 31;
    int j = blockIdx.x * 8 + warp;              // 0..2047
    const float* wr = wo + (long)j*DIM;
    float w[64];
    #pragma unroll
    for (int k = 0; k < 64; k++) w[k] = wr[lane + 32*k];
    float bias = wob[j];
    for (int b = 0; b < B; b++){
        const float* xb = xs + b*DIM;
        float s = 0.f;
        #pragma unroll
        for (int k = 0; k < 64; k++) s += w[k]*xb[lane + 32*k];
        #pragma unroll
        for (int o = 16; o; o >>= 1) s += __shfl_xor_sync(0xffffffffu, s, o);
        if (lane == 0) out[b*DIM + j] = s + bias;
    }
}

// ---------------- host launcher ----------------
extern "C" void kernel_launch(void* const* d_in, const int* in_sizes, int n_in,
                              void* d_out, int out_size){
    const float* x    = (const float*)d_in[0];
    // d_in[1] = start_pos (fixed 8191, implied by shapes) — unused
    const float* fcos = (const float*)d_in[2];
    const float* fsin = (const float*)d_in[3];
    const float* kvp  = (const float*)d_in[4];
    const float* pep  = (const float*)d_in[5];
    const float* wqa  = (const float*)d_in[6];
    const float* bqa  = (const float*)d_in[7];
    const float* qnw  = (const float*)d_in[8];
    const float* wqb  = (const float*)d_in[9];
    const float* bqb  = (const float*)d_in[10];
    const float* wkva = (const float*)d_in[11];
    const float* bkva = (const float*)d_in[12];
    const float* kvnw = (const float*)d_in[13];
    const float* wkvb = (const float*)d_in[14];
    const float* wo   = (const float*)d_in[15];
    const float* wob  = (const float*)d_in[16];
    float* out = (float*)d_out;

    const int SMEM_K1 = B*DIM*4;                    // 65536
    const int SMEM_K3 = B*QLR*4;                    // 49152
    const int SMEM_K5 = (2*H*DHEAD + 256 + 48)*4;   // ~74.9 KB
    const int SMEM_K7 = B*DIM*4;                    // 65536
    cudaFuncSetAttribute(k_proj_a,  cudaFuncAttributeMaxDynamicSharedMemorySize, SMEM_K1);
    cudaFuncSetAttribute(k_proj_qb, cudaFuncAttributeMaxDynamicSharedMemorySize, SMEM_K3);
    cudaFuncSetAttribute(k_attn,    cudaFuncAttributeMaxDynamicSharedMemorySize, SMEM_K5);
    cudaFuncSetAttribute(k_proj_o,  cudaFuncAttributeMaxDynamicSharedMemorySize, SMEM_K7);

    k_proj_a<<<(QLR+KVLR+DR)/8, 256, SMEM_K1>>>(x, wqa, bqa, wkva, bkva);
    k_norm_rope<<<B, 512>>>(qnw, kvnw, fcos, fsin);
    k_proj_qb<<<(H*(DN+DR))/8, 256, SMEM_K3>>>(wqb, bqb);
    { dim3 g(H, 5); k_qfull<<<g, 128>>>(wkvb, fcos, fsin); }
    { dim3 g(NCHUNK, B); k_attn<<<g, 512, SMEM_K5>>>(kvp, pep); }
    { dim3 g(H, B); k_reduce<<<g, 512>>>(wkvb); }
    k_proj_o<<<DIM/8, 256, SMEM_K7>>>(wo, wob, out);
}

// round 4
// speedup vs baseline: 1.6131x; 1.6131x over previous
#include <cuda_runtime.h>
#include <cuda_bf16.h>

// ---------------- problem constants ----------------
#define B 8
#define H 16
#define DIM 2048
#define QLR 1536
#define KVLR 512
#define DN 128
#define DR 64
#define DV 128
#define T_TOT 8192
#define T_PREFIX 8191
#define NCHUNK 64
#define CHUNK 128          // tokens per CTA in attention
#define TB 16              // tokens per inner block
#define NBLK (CHUNK/TB)    // 8
#define DHEAD 576          // 512 + 64
#define KSTR 584           // padded kv row stride in smem
#define SCALEF 0.07216878364870322f   // (DN+DR)^-0.5 = 192^-0.5

// ---------------- device scratch (no allocations allowed) ----------------
__device__ float g_qa  [B*QLR];
__device__ float g_kvpe[B*(KVLR+DR)];
__device__ float g_qan [B*QLR];
__device__ float g_kvn [B*KVLR];
__device__ float g_pen [B*DR];
__device__ float g_q   [B*H*(DN+DR)];
__device__ float g_qfull[B*H*DHEAD];
__device__ float g_pm  [B*NCHUNK*H];
__device__ float g_pl  [B*NCHUNK*H];
__device__ float g_pout[B*NCHUNK*H*KVLR];    // 16.8 MB
__device__ float g_out2[B*H*DV];

__device__ __forceinline__ float dot4(float4 a, float4 b){
    return a.x*b.x + a.y*b.y + a.z*b.z + a.w*b.w;
}

// ========== K1: qa = x @ wq_a^T + b ; kvpe = x @ wkv_a^T + b ==========
__global__ void k_proj_a(const float* __restrict__ x,
                         const float* __restrict__ wqa, const float* __restrict__ bqa,
                         const float* __restrict__ wkva, const float* __restrict__ bkva){
    extern __shared__ float xs[];               // 8*2048 floats
    int tid = threadIdx.x;
    for (int i = tid; i < B*DIM; i += blockDim.x) xs[i] = x[i];
    __syncthreads();
    int warp = tid >> 5, lane = tid & 31;
    int r = blockIdx.x * 8 + warp;
    if (r >= QLR + KVLR + DR) return;
    const float* wrow; float bias;
    if (r < QLR) { wrow = wqa + (long)r*DIM; bias = bqa[r]; }
    else         { wrow = wkva + (long)(r-QLR)*DIM; bias = bkva[r-QLR]; }
    float w[64];
    #pragma unroll
    for (int k = 0; k < 64; k++) w[k] = wrow[lane + 32*k];
    for (int b = 0; b < B; b++){
        const float* xb = xs + b*DIM;
        float s = 0.f;
        #pragma unroll
        for (int k = 0; k < 64; k++) s += w[k]*xb[lane + 32*k];
        #pragma unroll
        for (int o = 16; o; o >>= 1) s += __shfl_xor_sync(0xffffffffu, s, o);
        if (lane == 0){
            if (r < QLR) g_qa[b*QLR + r] = s + bias;
            else         g_kvpe[b*(KVLR+DR) + (r-QLR)] = s + bias;
        }
    }
}

// ========== K2: RMS-norm qa and kv; rope k_pe ==========
__global__ void k_norm_rope(const float* __restrict__ qnw, const float* __restrict__ kvnw,
                            const float* __restrict__ fcos, const float* __restrict__ fsin){
    int b = blockIdx.x, tid = threadIdx.x;      // 512 threads
    __shared__ float red[16];
    __shared__ float sq, skv;
    float s = 0.f;
    for (int i = tid; i < QLR; i += 512){ float v = g_qa[b*QLR+i]; s += v*v; }
    #pragma unroll
    for (int o = 16; o; o >>= 1) s += __shfl_xor_sync(0xffffffffu, s, o);
    if ((tid&31) == 0) red[tid>>5] = s;
    __syncthreads();
    if (tid == 0){ float t=0; for (int i=0;i<16;i++) t += red[i];
                   sq = rsqrtf(t*(1.f/QLR) + 1e-6f); }
    __syncthreads();
    float s2 = 0.f;
    { float v = (tid < KVLR) ? g_kvpe[b*(KVLR+DR)+tid] : 0.f; s2 = v*v; }
    #pragma unroll
    for (int o = 16; o; o >>= 1) s2 += __shfl_xor_sync(0xffffffffu, s2, o);
    if ((tid&31) == 0) red[tid>>5] = s2;
    __syncthreads();
    if (tid == 0){ float t=0; for (int i=0;i<16;i++) t += red[i];
                   skv = rsqrtf(t*(1.f/KVLR) + 1e-6f); }
    __syncthreads();
    for (int i = tid; i < QLR; i += 512) g_qan[b*QLR+i] = g_qa[b*QLR+i]*qnw[i]*sq;
    if (tid < KVLR) g_kvn[b*KVLR+tid] = g_kvpe[b*(KVLR+DR)+tid]*kvnw[tid]*skv;
    if (tid < DR){
        int i = tid >> 1;
        float xr = g_kvpe[b*(KVLR+DR)+KVLR+2*i];
        float xi = g_kvpe[b*(KVLR+DR)+KVLR+2*i+1];
        float c = fcos[i], sn = fsin[i];
        g_pen[b*DR+tid] = (tid&1) ? (xr*sn + xi*c) : (xr*c - xi*sn);
    }
}

// ========== K3: q = qa_n @ wq_b^T + b ==========
__global__ void k_proj_qb(const float* __restrict__ wqb, const float* __restrict__ bqb){
    extern __shared__ float qs[];
    int tid = threadIdx.x;
    for (int i = tid; i < B*QLR; i += blockDim.x) qs[i] = g_qan[i];
    __syncthreads();
    int warp = tid >> 5, lane = tid & 31;
    int r = blockIdx.x * 8 + warp;
    const float* wr = wqb + (long)r*QLR;
    float w[48];
    #pragma unroll
    for (int k = 0; k < 48; k++) w[k] = wr[lane + 32*k];
    float bias = bqb[r];
    for (int b = 0; b < B; b++){
        const float* xb = qs + b*QLR;
        float s = 0.f;
        #pragma unroll
        for (int k = 0; k < 48; k++) s += w[k]*xb[lane + 32*k];
        #pragma unroll
        for (int o = 16; o; o >>= 1) s += __shfl_xor_sync(0xffffffffu, s, o);
        if (lane == 0) g_q[b*(H*(DN+DR)) + r] = s + bias;
    }
}

// ========== K4: q_full = [q_nope @ wkv_b[:, :DN] (512) , rope(q_pe) (64)] ==========
// grid (H, 5), 512 threads. part<4: c-block of 128; each thread does 2 batches.
__global__ void k_qfull(const float* __restrict__ wkvb,
                        const float* __restrict__ fcos, const float* __restrict__ fsin){
    int h = blockIdx.x, part = blockIdx.y, tid = threadIdx.x;
    if (part < 4){
        __shared__ float qn[B][DN];
        for (int i = tid; i < B*DN; i += 512){ int b = i>>7, d = i&127;
            qn[b][d] = g_q[b*(H*(DN+DR)) + h*(DN+DR) + d]; }
        __syncthreads();
        int c = part*128 + (tid & 127);
        int b0 = tid >> 7;                    // 0..3 -> handles b0 and b0+4
        float a0 = 0.f, a1 = 0.f;
        #pragma unroll 4
        for (int d = 0; d < DN; d++){
            float w = wkvb[(long)(h*(DN+DV) + d)*KVLR + c];
            a0 += qn[b0][d]*w;
            a1 += qn[b0+4][d]*w;
        }
        g_qfull[(b0*H + h)*DHEAD + c]     = a0;
        g_qfull[((b0+4)*H + h)*DHEAD + c] = a1;
    } else {
        if (tid < DR){
            int i = tid >> 1;
            float c = fcos[i], sn = fsin[i];
            for (int b = 0; b < B; b++){
                float xr = g_q[b*(H*(DN+DR)) + h*(DN+DR) + DN + 2*i];
                float xi = g_q[b*(H*(DN+DR)) + h*(DN+DR) + DN + 2*i + 1];
                g_qfull[(b*H + h)*DHEAD + KVLR + tid] =
                    (tid&1) ? (xr*sn + xi*c) : (xr*c - xi*sn);
            }
        }
    }
}

// ---------- kv row gather helper (handles the new token at position 8191) ----------
__device__ __forceinline__ float4 load_kv4(const float* __restrict__ kvp,
                                           const float* __restrict__ pep,
                                           int b, int tg, int j){
    if (tg == T_PREFIX){
        if (j < 128) return *(const float4*)(g_kvn + b*KVLR + 4*j);
        return *(const float4*)(g_pen + b*DR + 4*(j-128));
    }
    if (j < 128) return *(const float4*)(kvp + ((long)b*T_PREFIX + tg)*KVLR + 4*j);
    return *(const float4*)(pep + ((long)b*T_PREFIX + tg)*DR + 4*(j-128));
}

// ========== K5: flash attention, register-tiled, double-buffered ==========
// grid (64, 8), 512 threads (16 warps).
// score:      warp = (hg, tg) tile -> 4 heads x 4 tokens, lane-sliced dots over 576 dims
// accumulate: warp = (hg, cg) tile -> 4 heads x 128 cols, float4 per lane
__global__ void __launch_bounds__(512, 1) k_attn(const float* __restrict__ kvp,
                                                 const float* __restrict__ pep){
    extern __shared__ float sm[];
    float* q_s = sm;                         // H*DHEAD = 9216
    float* kv0 = sm + H*DHEAD;               // TB*KSTR
    float* kv1 = kv0 + TB*KSTR;              // TB*KSTR
    float* p_s = kv1 + TB*KSTR;              // 256
    float* s_m = p_s + 256;                  // 16
    float* s_l = s_m + 16;                   // 16
    float* s_c = s_l + 16;                   // 16
    int chunk = blockIdx.x, b = blockIdx.y, tid = threadIdx.x;
    int warp = tid >> 5, lane = tid & 31;

    for (int i = tid; i < H*DHEAD/4; i += 512)
        ((float4*)q_s)[i] = ((const float4*)(g_qfull + b*H*DHEAD))[i];
    if (tid < H){ s_m[tid] = -1e30f; s_l[tid] = 0.f; }

    float4 acc4[4];
    #pragma unroll
    for (int h = 0; h < 4; h++) acc4[h] = make_float4(0.f,0.f,0.f,0.f);

    // prologue: load block 0 directly into kv0
    {
        int t0 = chunk*CHUNK;
        #pragma unroll
        for (int k = 0; k < 4; k++){
            int i = tid + 512*k; int t = i/144, j = i%144;
            *(float4*)(kv0 + t*KSTR + 4*j) = load_kv4(kvp, pep, b, t0+t, j);
        }
        if (tid < 256){
            int i = tid + 2048; int t = i/144, j = i%144;
            *(float4*)(kv0 + t*KSTR + 4*j) = load_kv4(kvp, pep, b, t0+t, j);
        }
    }
    __syncthreads();

    int hgS = warp >> 2, tg4 = (warp & 3)*4;       // score tile
    int hgA = warp >> 2, cg  = warp & 3;           // accumulate tile
    int c0 = cg*128 + 4*lane;

    for (int blk = 0; blk < NBLK; blk++){
        float* kvc = (blk & 1) ? kv1 : kv0;
        float* kvn = (blk & 1) ? kv0 : kv1;
        bool doPre = (blk + 1 < NBLK);
        int nt0 = chunk*CHUNK + (blk+1)*TB;

        // prefetch next block into registers (LDG latency overlaps compute)
        float4 pre[5];
        if (doPre){
            #pragma unroll
            for (int k = 0; k < 4; k++){
                int i = tid + 512*k; int t = i/144, j = i%144;
                pre[k] = load_kv4(kvp, pep, b, nt0+t, j);
            }
            if (tid < 256){
                int i = tid + 2048; int t = i/144, j = i%144;
                pre[4] = load_kv4(kvp, pep, b, nt0+t, j);
            }
        }

        // ---- scores: 4 heads x 4 tokens per warp ----
        {
            float sc[16];
            #pragma unroll
            for (int j = 0; j < 16; j++) sc[j] = 0.f;
            const float* qb = q_s + (hgS*4)*DHEAD;
            const float* kb = kvc + tg4*KSTR;
            #pragma unroll
            for (int i = 0; i < 4; i++){
                int d0 = i*128 + 4*lane;
                float4 q0 = *(const float4*)(qb + d0);
                float4 q1 = *(const float4*)(qb + DHEAD + d0);
                float4 q2 = *(const float4*)(qb + 2*DHEAD + d0);
                float4 q3 = *(const float4*)(qb + 3*DHEAD + d0);
                float4 k0 = *(const float4*)(kb + d0);
                float4 k1 = *(const float4*)(kb + KSTR + d0);
                float4 k2 = *(const float4*)(kb + 2*KSTR + d0);
                float4 k3 = *(const float4*)(kb + 3*KSTR + d0);
                sc[0]+=dot4(q0,k0);  sc[1]+=dot4(q0,k1);  sc[2]+=dot4(q0,k2);  sc[3]+=dot4(q0,k3);
                sc[4]+=dot4(q1,k0);  sc[5]+=dot4(q1,k1);  sc[6]+=dot4(q1,k2);  sc[7]+=dot4(q1,k3);
                sc[8]+=dot4(q2,k0);  sc[9]+=dot4(q2,k1);  sc[10]+=dot4(q2,k2); sc[11]+=dot4(q2,k3);
                sc[12]+=dot4(q3,k0); sc[13]+=dot4(q3,k1); sc[14]+=dot4(q3,k2); sc[15]+=dot4(q3,k3);
            }
            if (lane < 16){
                int d0 = 512 + 4*lane;
                float4 q0 = *(const float4*)(qb + d0);
                float4 q1 = *(const float4*)(qb + DHEAD + d0);
                float4 q2 = *(const float4*)(qb + 2*DHEAD + d0);
                float4 q3 = *(const float4*)(qb + 3*DHEAD + d0);
                float4 k0 = *(const float4*)(kb + d0);
                float4 k1 = *(const float4*)(kb + KSTR + d0);
                float4 k2 = *(const float4*)(kb + 2*KSTR + d0);
                float4 k3 = *(const float4*)(kb + 3*KSTR + d0);
                sc[0]+=dot4(q0,k0);  sc[1]+=dot4(q0,k1);  sc[2]+=dot4(q0,k2);  sc[3]+=dot4(q0,k3);
                sc[4]+=dot4(q1,k0);  sc[5]+=dot4(q1,k1);  sc[6]+=dot4(q1,k2);  sc[7]+=dot4(q1,k3);
                sc[8]+=dot4(q2,k0);  sc[9]+=dot4(q2,k1);  sc[10]+=dot4(q2,k2); sc[11]+=dot4(q2,k3);
                sc[12]+=dot4(q3,k0); sc[13]+=dot4(q3,k1); sc[14]+=dot4(q3,k2); sc[15]+=dot4(q3,k3);
            }
            #pragma unroll
            for (int j = 0; j < 16; j++){
                float v = sc[j];
                #pragma unroll
                for (int o = 16; o; o >>= 1) v += __shfl_xor_sync(0xffffffffu, v, o);
                if (lane == j){
                    int hh = hgS*4 + (j >> 2), tt = tg4 + (j & 3);
                    p_s[hh*TB + tt] = v * SCALEF;
                }
            }
        }
        __syncthreads();

        // ---- online softmax (16 threads, one per head) ----
        if (tid < H){
            int h = tid;
            float bm = -1e30f;
            #pragma unroll
            for (int t = 0; t < TB; t++) bm = fmaxf(bm, p_s[h*TB + t]);
            float mo = s_m[h], mn = fmaxf(mo, bm);
            float corr = __expf(mo - mn);
            float sum = 0.f;
            #pragma unroll
            for (int t = 0; t < TB; t++){
                float p = __expf(p_s[h*TB + t] - mn);
                p_s[h*TB + t] = p; sum += p;
            }
            s_l[h] = s_l[h]*corr + sum; s_m[h] = mn; s_c[h] = corr;
        }
        __syncthreads();

        // ---- accumulate: 4 heads x 128 cols per warp ----
        {
            float c_0 = s_c[hgA*4+0], c_1 = s_c[hgA*4+1],
                  c_2 = s_c[hgA*4+2], c_3 = s_c[hgA*4+3];
            acc4[0].x*=c_0; acc4[0].y*=c_0; acc4[0].z*=c_0; acc4[0].w*=c_0;
            acc4[1].x*=c_1; acc4[1].y*=c_1; acc4[1].z*=c_1; acc4[1].w*=c_1;
            acc4[2].x*=c_2; acc4[2].y*=c_2; acc4[2].z*=c_2; acc4[2].w*=c_2;
            acc4[3].x*=c_3; acc4[3].y*=c_3; acc4[3].z*=c_3; acc4[3].w*=c_3;
            #pragma unroll
            for (int t = 0; t < TB; t++){
                float4 kv = *(const float4*)(kvc + t*KSTR + c0);
                float p0 = p_s[(hgA*4+0)*TB + t];
                float p1 = p_s[(hgA*4+1)*TB + t];
                float p2 = p_s[(hgA*4+2)*TB + t];
                float p3 = p_s[(hgA*4+3)*TB + t];
                acc4[0].x += p0*kv.x; acc4[0].y += p0*kv.y; acc4[0].z += p0*kv.z; acc4[0].w += p0*kv.w;
                acc4[1].x += p1*kv.x; acc4[1].y += p1*kv.y; acc4[1].z += p1*kv.z; acc4[1].w += p1*kv.w;
                acc4[2].x += p2*kv.x; acc4[2].y += p2*kv.y; acc4[2].z += p2*kv.z; acc4[2].w += p2*kv.w;
                acc4[3].x += p3*kv.x; acc4[3].y += p3*kv.y; acc4[3].z += p3*kv.z; acc4[3].w += p3*kv.w;
            }
        }

        // store prefetched block to the other buffer
        if (doPre){
            #pragma unroll
            for (int k = 0; k < 4; k++){
                int i = tid + 512*k; int t = i/144, j = i%144;
                *(float4*)(kvn + t*KSTR + 4*j) = pre[k];
            }
            if (tid < 256){
                int i = tid + 2048; int t = i/144, j = i%144;
                *(float4*)(kvn + t*KSTR + 4*j) = pre[4];
            }
        }
        __syncthreads();
    }

    long base = ((long)(b*NCHUNK + chunk)*H + hgA*4)*KVLR + c0;
    #pragma unroll
    for (int h = 0; h < 4; h++)
        *(float4*)(g_pout + base + (long)h*KVLR) = acc4[h];
    if (tid < H){
        g_pm[(b*NCHUNK + chunk)*H + tid] = s_m[tid];
        g_pl[(b*NCHUNK + chunk)*H + tid] = s_l[tid];
    }
}

// ========== K6: combine split-softmax partials + V projection ==========
// grid (16, 8): h = bx, b = by; 512 threads.
__global__ void k_reduce(const float* __restrict__ wkvb){
    int h = blockIdx.x, b = blockIdx.y, tid = threadIdx.x;
    __shared__ float sm_m[NCHUNK], sm_l[NCHUNK], wk[NCHUNK];
    __shared__ float so[KVLR];
    if (tid < NCHUNK){
        sm_m[tid] = g_pm[(b*NCHUNK + tid)*H + h];
        sm_l[tid] = g_pl[(b*NCHUNK + tid)*H + h];
    }
    __syncthreads();
    if (tid == 0){
        float M = -1e30f;
        for (int k = 0; k < NCHUNK; k++) M = fmaxf(M, sm_m[k]);
        float L = 0.f;
        for (int k = 0; k < NCHUNK; k++){ wk[k] = __expf(sm_m[k]-M)*sm_l[k]; L += wk[k]; }
        float inv = 1.f/L;
        for (int k = 0; k < NCHUNK; k++) wk[k] = __expf(sm_m[k]-M)*inv;
    }
    __syncthreads();
    float out = 0.f;
    #pragma unroll 4
    for (int k = 0; k < NCHUNK; k++)
        out += wk[k]*g_pout[((long)(b*NCHUNK + k)*H + h)*KVLR + tid];
    so[tid] = out;
    __syncthreads();
    int d = tid >> 2, part = tid & 3;
    const float* wr = wkvb + (long)(h*(DN+DV) + DN + d)*KVLR + part*128;
    const float* sp = so + part*128;
    float s = 0.f;
    #pragma unroll 8
    for (int c = 0; c < 128; c++) s += sp[c]*wr[c];
    s += __shfl_xor_sync(0xffffffffu, s, 1);
    s += __shfl_xor_sync(0xffffffffu, s, 2);
    if (part == 0) g_out2[(b*H + h)*DV + d] = s;
}

// ========== K7: y = out2 @ wo^T + wo_b ==========
__global__ void k_proj_o(const float* __restrict__ wo, const float* __restrict__ wob,
                         float* __restrict__ out){
    extern __shared__ float xs[];
    int tid = threadIdx.x;
    for (int i = tid; i < B*DIM; i += blockDim.x) xs[i] = g_out2[i];
    __syncthreads();
    int warp = tid >> 5, lane = tid & 31;
    int j = blockIdx.x * 8 + warp;
    const float* wr = wo + (long)j*DIM;
    float w[64];
    #pragma unroll
    for (int k = 0; k < 64; k++) w[k] = wr[lane + 32*k];
    float bias = wob[j];
    for (int b = 0; b < B; b++){
        const float* xb = xs + b*DIM;
        float s = 0.f;
        #pragma unroll
        for (int k = 0; k < 64; k++) s += w[k]*xb[lane + 32*k];
        #pragma unroll
        for (int o = 16; o; o >>= 1) s += __shfl_xor_sync(0xffffffffu, s, o);
        if (lane == 0) out[b*DIM + j] = s + bias;
    }
}

// ---------------- host launcher ----------------
extern "C" void kernel_launch(void* const* d_in, const int* in_sizes, int n_in,
                              void* d_out, int out_size){
    const float* x    = (const float*)d_in[0];
    const float* fcos = (const float*)d_in[2];
    const float* fsin = (const float*)d_in[3];
    const float* kvp  = (const float*)d_in[4];
    const float* pep  = (const float*)d_in[5];
    const float* wqa  = (const float*)d_in[6];
    const float* bqa  = (const float*)d_in[7];
    const float* qnw  = (const float*)d_in[8];
    const float* wqb  = (const float*)d_in[9];
    const float* bqb  = (const float*)d_in[10];
    const float* wkva = (const float*)d_in[11];
    const float* bkva = (const float*)d_in[12];
    const float* kvnw = (const float*)d_in[13];
    const float* wkvb = (const float*)d_in[14];
    const float* wo   = (const float*)d_in[15];
    const float* wob  = (const float*)d_in[16];
    float* out = (float*)d_out;

    const int SMEM_K1 = B*DIM*4;
    const int SMEM_K3 = B*QLR*4;
    const int SMEM_K5 = (H*DHEAD + 2*TB*KSTR + 256 + 48)*4;   // ~113 KB
    const int SMEM_K7 = B*DIM*4;
    cudaFuncSetAttribute(k_proj_a,  cudaFuncAttributeMaxDynamicSharedMemorySize, SMEM_K1);
    cudaFuncSetAttribute(k_proj_qb, cudaFuncAttributeMaxDynamicSharedMemorySize, SMEM_K3);
    cudaFuncSetAttribute(k_attn,    cudaFuncAttributeMaxDynamicSharedMemorySize, SMEM_K5);
    cudaFuncSetAttribute(k_proj_o,  cudaFuncAttributeMaxDynamicSharedMemorySize, SMEM_K7);

    k_proj_a<<<(QLR+KVLR+DR)/8, 256, SMEM_K1>>>(x, wqa, bqa, wkva, bkva);
    k_norm_rope<<<B, 512>>>(qnw, kvnw, fcos, fsin);
    k_proj_qb<<<(H*(DN+DR))/8, 256, SMEM_K3>>>(wqb, bqb);
    { dim3 g(H, 5); k_qfull<<<g, 512>>>(wkvb, fcos, fsin); }
    { dim3 g(NCHUNK, B); k_attn<<<g, 512, SMEM_K5>>>(kvp, pep); }
    { dim3 g(H, B); k_reduce<<<g, 512>>>(wkvb); }
    k_proj_o<<<DIM/8, 256, SMEM_K7>>>(wo, wob, out);
}

// round 5
// speedup vs baseline: 1.6447x; 1.0196x over previous
#include <cuda_runtime.h>
#include <cuda_bf16.h>

// ---------------- problem constants ----------------
#define B 8
#define H 16
#define DIM 2048
#define QLR 1536
#define KVLR 512
#define DN 128
#define DR 64
#define DV 128
#define T_TOT 8192
#define T_PREFIX 8191
#define NCHUNK 64
#define CHUNK 128          // tokens per CTA in attention
#define TB 16              // tokens per inner block
#define NBLK (CHUNK/TB)    // 8
#define DHEAD 576          // 512 + 64
#define KSTR 584           // padded kv row stride in smem
#define SCALEF 0.07216878364870322f   // (DN+DR)^-0.5 = 192^-0.5

typedef unsigned long long u64;

// ---------------- device scratch (no allocations allowed) ----------------
__device__ float g_qa  [B*QLR];
__device__ float g_kvpe[B*(KVLR+DR)];
__device__ float g_qan [B*QLR];
__device__ float g_kvn [B*KVLR];
__device__ float g_pen [B*DR];
__device__ float g_q   [B*H*(DN+DR)];
__device__ float g_qfull[B*H*DHEAD];
__device__ float g_pm  [B*NCHUNK*H];
__device__ float g_pl  [B*NCHUNK*H];
__device__ float g_pout[B*NCHUNK*H*KVLR];    // 16.8 MB
__device__ float g_out2[B*H*DV];

// ---------------- packed f32x2 helpers (Blackwell FFMA2) ----------------
__device__ __forceinline__ u64 pk2(float lo, float hi){
    u64 r; asm("mov.b64 %0, {%1,%2};" : "=l"(r) : "f"(lo), "f"(hi)); return r;
}
__device__ __forceinline__ void upk2(u64 v, float& lo, float& hi){
    asm("mov.b64 {%0,%1}, %2;" : "=f"(lo), "=f"(hi) : "l"(v));
}
__device__ __forceinline__ u64 fma2(u64 a, u64 b, u64 c){
    u64 d; asm("fma.rn.f32x2 %0, %1, %2, %3;" : "=l"(d) : "l"(a), "l"(b), "l"(c)); return d;
}
__device__ __forceinline__ u64 mul2(u64 a, u64 b){
    u64 d; asm("mul.rn.f32x2 %0, %1, %2;" : "=l"(d) : "l"(a), "l"(b)); return d;
}

// ========== K1: qa = x @ wq_a^T + b ; kvpe = x @ wkv_a^T + b ==========
__global__ void k_proj_a(const float* __restrict__ x,
                         const float* __restrict__ wqa, const float* __restrict__ bqa,
                         const float* __restrict__ wkva, const float* __restrict__ bkva){
    extern __shared__ float xs[];
    int tid = threadIdx.x;
    for (int i = tid; i < B*DIM; i += blockDim.x) xs[i] = x[i];
    __syncthreads();
    int warp = tid >> 5, lane = tid & 31;
    int r = blockIdx.x * 8 + warp;
    if (r >= QLR + KVLR + DR) return;
    const float* wrow; float bias;
    if (r < QLR) { wrow = wqa + (long)r*DIM; bias = bqa[r]; }
    else         { wrow = wkva + (long)(r-QLR)*DIM; bias = bkva[r-QLR]; }
    float w[64];
    #pragma unroll
    for (int k = 0; k < 64; k++) w[k] = wrow[lane + 32*k];
    for (int b = 0; b < B; b++){
        const float* xb = xs + b*DIM;
        float s = 0.f;
        #pragma unroll
        for (int k = 0; k < 64; k++) s += w[k]*xb[lane + 32*k];
        #pragma unroll
        for (int o = 16; o; o >>= 1) s += __shfl_xor_sync(0xffffffffu, s, o);
        if (lane == 0){
            if (r < QLR) g_qa[b*QLR + r] = s + bias;
            else         g_kvpe[b*(KVLR+DR) + (r-QLR)] = s + bias;
        }
    }
}

// ========== K2: RMS-norm qa and kv; rope k_pe ==========
__global__ void k_norm_rope(const float* __restrict__ qnw, const float* __restrict__ kvnw,
                            const float* __restrict__ fcos, const float* __restrict__ fsin){
    int b = blockIdx.x, tid = threadIdx.x;      // 512 threads
    __shared__ float red[16];
    __shared__ float sq, skv;
    float s = 0.f;
    for (int i = tid; i < QLR; i += 512){ float v = g_qa[b*QLR+i]; s += v*v; }
    #pragma unroll
    for (int o = 16; o; o >>= 1) s += __shfl_xor_sync(0xffffffffu, s, o);
    if ((tid&31) == 0) red[tid>>5] = s;
    __syncthreads();
    if (tid == 0){ float t=0; for (int i=0;i<16;i++) t += red[i];
                   sq = rsqrtf(t*(1.f/QLR) + 1e-6f); }
    __syncthreads();
    float s2 = 0.f;
    { float v = (tid < KVLR) ? g_kvpe[b*(KVLR+DR)+tid] : 0.f; s2 = v*v; }
    #pragma unroll
    for (int o = 16; o; o >>= 1) s2 += __shfl_xor_sync(0xffffffffu, s2, o);
    if ((tid&31) == 0) red[tid>>5] = s2;
    __syncthreads();
    if (tid == 0){ float t=0; for (int i=0;i<16;i++) t += red[i];
                   skv = rsqrtf(t*(1.f/KVLR) + 1e-6f); }
    __syncthreads();
    for (int i = tid; i < QLR; i += 512) g_qan[b*QLR+i] = g_qa[b*QLR+i]*qnw[i]*sq;
    if (tid < KVLR) g_kvn[b*KVLR+tid] = g_kvpe[b*(KVLR+DR)+tid]*kvnw[tid]*skv;
    if (tid < DR){
        int i = tid >> 1;
        float xr = g_kvpe[b*(KVLR+DR)+KVLR+2*i];
        float xi = g_kvpe[b*(KVLR+DR)+KVLR+2*i+1];
        float c = fcos[i], sn = fsin[i];
        g_pen[b*DR+tid] = (tid&1) ? (xr*sn + xi*c) : (xr*c - xi*sn);
    }
}

// ========== K3: q = qa_n @ wq_b^T + b ==========
__global__ void k_proj_qb(const float* __restrict__ wqb, const float* __restrict__ bqb){
    extern __shared__ float qs[];
    int tid = threadIdx.x;
    for (int i = tid; i < B*QLR; i += blockDim.x) qs[i] = g_qan[i];
    __syncthreads();
    int warp = tid >> 5, lane = tid & 31;
    int r = blockIdx.x * 8 + warp;
    const float* wr = wqb + (long)r*QLR;
    float w[48];
    #pragma unroll
    for (int k = 0; k < 48; k++) w[k] = wr[lane + 32*k];
    float bias = bqb[r];
    for (int b = 0; b < B; b++){
        const float* xb = qs + b*QLR;
        float s = 0.f;
        #pragma unroll
        for (int k = 0; k < 48; k++) s += w[k]*xb[lane + 32*k];
        #pragma unroll
        for (int o = 16; o; o >>= 1) s += __shfl_xor_sync(0xffffffffu, s, o);
        if (lane == 0) g_q[b*(H*(DN+DR)) + r] = s + bias;
    }
}

// ========== K4: q_full = [q_nope @ wkv_b[:, :DN] (512) , rope(q_pe) (64)] ==========
// grid (H, 5), 512 threads. parts 0-3: 4 d-groups x 128 c, MLP-unrolled LDG + smem reduce.
__global__ void k_qfull(const float* __restrict__ wkvb,
                        const float* __restrict__ fcos, const float* __restrict__ fsin){
    int h = blockIdx.x, part = blockIdx.y, tid = threadIdx.x;
    if (part < 4){
        __shared__ float qn[B][DN];
        __shared__ float red[4][B][129];
        for (int i = tid; i < B*DN; i += 512){ int b = i>>7, d = i&127;
            qn[b][d] = g_q[b*(H*(DN+DR)) + h*(DN+DR) + d]; }
        __syncthreads();
        int dg = tid >> 7, cc = tid & 127;
        int c = part*128 + cc;
        float acc[B];
        #pragma unroll
        for (int b = 0; b < B; b++) acc[b] = 0.f;
        const float* wp = wkvb + (long)(h*(DN+DV) + dg*32)*KVLR + c;
        #pragma unroll
        for (int ds = 0; ds < 32; ds += 4){
            float w0 = wp[(long)(ds+0)*KVLR];
            float w1 = wp[(long)(ds+1)*KVLR];
            float w2 = wp[(long)(ds+2)*KVLR];
            float w3 = wp[(long)(ds+3)*KVLR];
            #pragma unroll
            for (int b = 0; b < B; b++){
                float4 q = *(const float4*)(&qn[b][dg*32 + ds]);
                acc[b] += q.x*w0 + q.y*w1 + q.z*w2 + q.w*w3;
            }
        }
        #pragma unroll
        for (int b = 0; b < B; b++) red[dg][b][cc] = acc[b];
        __syncthreads();
        for (int i = tid; i < B*128; i += 512){
            int b = i >> 7, c2 = i & 127;
            float s = red[0][b][c2] + red[1][b][c2] + red[2][b][c2] + red[3][b][c2];
            g_qfull[(b*H + h)*DHEAD + part*128 + c2] = s;
        }
    } else {
        if (tid < DR){
            int i = tid >> 1;
            float c = fcos[i], sn = fsin[i];
            for (int b = 0; b < B; b++){
                float xr = g_q[b*(H*(DN+DR)) + h*(DN+DR) + DN + 2*i];
                float xi = g_q[b*(H*(DN+DR)) + h*(DN+DR) + DN + 2*i + 1];
                g_qfull[(b*H + h)*DHEAD + KVLR + tid] =
                    (tid&1) ? (xr*sn + xi*c) : (xr*c - xi*sn);
            }
        }
    }
}

// ---------- kv row gather helper (handles the new token at position 8191) ----------
__device__ __forceinline__ float4 load_kv4(const float* __restrict__ kvp,
                                           const float* __restrict__ pep,
                                           int b, int tg, int j){
    if (tg == T_PREFIX){
        if (j < 128) return *(const float4*)(g_kvn + b*KVLR + 4*j);
        return *(const float4*)(g_pen + b*DR + 4*(j-128));
    }
    if (j < 128) return *(const float4*)(kvp + ((long)b*T_PREFIX + tg)*KVLR + 4*j);
    return *(const float4*)(pep + ((long)b*T_PREFIX + tg)*DR + 4*(j-128));
}

// ========== K5: flash attention, register-tiled, f32x2 packed math ==========
// grid (64, 8), 512 threads (16 warps).
__global__ void __launch_bounds__(512, 1) k_attn(const float* __restrict__ kvp,
                                                 const float* __restrict__ pep){
    extern __shared__ float sm[];
    float* q_s = sm;                         // H*DHEAD = 9216
    float* kv0 = sm + H*DHEAD;               // TB*KSTR
    float* kv1 = kv0 + TB*KSTR;              // TB*KSTR
    float* p_s = kv1 + TB*KSTR;              // 256 raw scores
    u64*  p_s2 = (u64*)(p_s + 256);          // 256 u64 packed probs (512 floats)
    float* s_m = p_s + 256 + 512;            // 16
    float* s_l = s_m + 16;                   // 16
    float* s_c = s_l + 16;                   // 16
    int chunk = blockIdx.x, b = blockIdx.y, tid = threadIdx.x;
    int warp = tid >> 5, lane = tid & 31;

    for (int i = tid; i < H*DHEAD/4; i += 512)
        ((float4*)q_s)[i] = ((const float4*)(g_qfull + b*H*DHEAD))[i];
    if (tid < H){ s_m[tid] = -1e30f; s_l[tid] = 0.f; }

    u64 acc2[8];                             // 4 heads x 4 cols (2 packed pairs each)
    #pragma unroll
    for (int i = 0; i < 8; i++) acc2[i] = 0ull;

    // prologue: load block 0 into kv0
    {
        int t0 = chunk*CHUNK;
        #pragma unroll
        for (int k = 0; k < 4; k++){
            int i = tid + 512*k; int t = i/144, j = i%144;
            *(float4*)(kv0 + t*KSTR + 4*j) = load_kv4(kvp, pep, b, t0+t, j);
        }
        if (tid < 256){
            int i = tid + 2048; int t = i/144, j = i%144;
            *(float4*)(kv0 + t*KSTR + 4*j) = load_kv4(kvp, pep, b, t0+t, j);
        }
    }
    __syncthreads();

    int hgS = warp >> 2, tg4 = (warp & 3)*4;       // score tile: 4 heads x 4 tokens
    int hgA = warp >> 2, cg  = warp & 3;           // accum tile: 4 heads x 128 cols
    int c0 = cg*128 + 4*lane;

    for (int blk = 0; blk < NBLK; blk++){
        float* kvc = (blk & 1) ? kv1 : kv0;
        float* kvn = (blk & 1) ? kv0 : kv1;
        bool doPre = (blk + 1 < NBLK);
        int nt0 = chunk*CHUNK + (blk+1)*TB;

        float4 pre[5];
        if (doPre){
            #pragma unroll
            for (int k = 0; k < 4; k++){
                int i = tid + 512*k; int t = i/144, j = i%144;
                pre[k] = load_kv4(kvp, pep, b, nt0+t, j);
            }
            if (tid < 256){
                int i = tid + 2048; int t = i/144, j = i%144;
                pre[4] = load_kv4(kvp, pep, b, nt0+t, j);
            }
        }

        // ---- scores: 4 heads x 4 tokens per warp, f32x2 packed FMA ----
        {
            u64 sc2[16];
            #pragma unroll
            for (int j = 0; j < 16; j++) sc2[j] = 0ull;
            const float* qb = q_s + (hgS*4)*DHEAD;
            const float* kb = kvc + tg4*KSTR;
            #pragma unroll
            for (int i = 0; i < 4; i++){
                int d0 = i*128 + 4*lane;
                ulonglong2 q0 = *(const ulonglong2*)(qb + d0);
                ulonglong2 q1 = *(const ulonglong2*)(qb + DHEAD + d0);
                ulonglong2 q2 = *(const ulonglong2*)(qb + 2*DHEAD + d0);
                ulonglong2 q3 = *(const ulonglong2*)(qb + 3*DHEAD + d0);
                ulonglong2 k0 = *(const ulonglong2*)(kb + d0);
                ulonglong2 k1 = *(const ulonglong2*)(kb + KSTR + d0);
                ulonglong2 k2 = *(const ulonglong2*)(kb + 2*KSTR + d0);
                ulonglong2 k3 = *(const ulonglong2*)(kb + 3*KSTR + d0);
                sc2[0]=fma2(q0.x,k0.x,sc2[0]); sc2[0]=fma2(q0.y,k0.y,sc2[0]);
                sc2[1]=fma2(q0.x,k1.x,sc2[1]); sc2[1]=fma2(q0.y,k1.y,sc2[1]);
                sc2[2]=fma2(q0.x,k2.x,sc2[2]); sc2[2]=fma2(q0.y,k2.y,sc2[2]);
                sc2[3]=fma2(q0.x,k3.x,sc2[3]); sc2[3]=fma2(q0.y,k3.y,sc2[3]);
                sc2[4]=fma2(q1.x,k0.x,sc2[4]); sc2[4]=fma2(q1.y,k0.y,sc2[4]);
                sc2[5]=fma2(q1.x,k1.x,sc2[5]); sc2[5]=fma2(q1.y,k1.y,sc2[5]);
                sc2[6]=fma2(q1.x,k2.x,sc2[6]); sc2[6]=fma2(q1.y,k2.y,sc2[6]);
                sc2[7]=fma2(q1.x,k3.x,sc2[7]); sc2[7]=fma2(q1.y,k3.y,sc2[7]);
                sc2[8]=fma2(q2.x,k0.x,sc2[8]); sc2[8]=fma2(q2.y,k0.y,sc2[8]);
                sc2[9]=fma2(q2.x,k1.x,sc2[9]); sc2[9]=fma2(q2.y,k1.y,sc2[9]);
                sc2[10]=fma2(q2.x,k2.x,sc2[10]); sc2[10]=fma2(q2.y,k2.y,sc2[10]);
                sc2[11]=fma2(q2.x,k3.x,sc2[11]); sc2[11]=fma2(q2.y,k3.y,sc2[11]);
                sc2[12]=fma2(q3.x,k0.x,sc2[12]); sc2[12]=fma2(q3.y,k0.y,sc2[12]);
                sc2[13]=fma2(q3.x,k1.x,sc2[13]); sc2[13]=fma2(q3.y,k1.y,sc2[13]);
                sc2[14]=fma2(q3.x,k2.x,sc2[14]); sc2[14]=fma2(q3.y,k2.y,sc2[14]);
                sc2[15]=fma2(q3.x,k3.x,sc2[15]); sc2[15]=fma2(q3.y,k3.y,sc2[15]);
            }
            if (lane < 16){
                int d0 = 512 + 4*lane;
                ulonglong2 q0 = *(const ulonglong2*)(qb + d0);
                ulonglong2 q1 = *(const ulonglong2*)(qb + DHEAD + d0);
                ulonglong2 q2 = *(const ulonglong2*)(qb + 2*DHEAD + d0);
                ulonglong2 q3 = *(const ulonglong2*)(qb + 3*DHEAD + d0);
                ulonglong2 k0 = *(const ulonglong2*)(kb + d0);
                ulonglong2 k1 = *(const ulonglong2*)(kb + KSTR + d0);
                ulonglong2 k2 = *(const ulonglong2*)(kb + 2*KSTR + d0);
                ulonglong2 k3 = *(const ulonglong2*)(kb + 3*KSTR + d0);
                sc2[0]=fma2(q0.x,k0.x,sc2[0]); sc2[0]=fma2(q0.y,k0.y,sc2[0]);
                sc2[1]=fma2(q0.x,k1.x,sc2[1]); sc2[1]=fma2(q0.y,k1.y,sc2[1]);
                sc2[2]=fma2(q0.x,k2.x,sc2[2]); sc2[2]=fma2(q0.y,k2.y,sc2[2]);
                sc2[3]=fma2(q0.x,k3.x,sc2[3]); sc2[3]=fma2(q0.y,k3.y,sc2[3]);
                sc2[4]=fma2(q1.x,k0.x,sc2[4]); sc2[4]=fma2(q1.y,k0.y,sc2[4]);
                sc2[5]=fma2(q1.x,k1.x,sc2[5]); sc2[5]=fma2(q1.y,k1.y,sc2[5]);
                sc2[6]=fma2(q1.x,k2.x,sc2[6]); sc2[6]=fma2(q1.y,k2.y,sc2[6]);
                sc2[7]=fma2(q1.x,k3.x,sc2[7]); sc2[7]=fma2(q1.y,k3.y,sc2[7]);
                sc2[8]=fma2(q2.x,k0.x,sc2[8]); sc2[8]=fma2(q2.y,k0.y,sc2[8]);
                sc2[9]=fma2(q2.x,k1.x,sc2[9]); sc2[9]=fma2(q2.y,k1.y,sc2[9]);
                sc2[10]=fma2(q2.x,k2.x,sc2[10]); sc2[10]=fma2(q2.y,k2.y,sc2[10]);
                sc2[11]=fma2(q2.x,k3.x,sc2[11]); sc2[11]=fma2(q2.y,k3.y,sc2[11]);
                sc2[12]=fma2(q3.x,k0.x,sc2[12]); sc2[12]=fma2(q3.y,k0.y,sc2[12]);
                sc2[13]=fma2(q3.x,k1.x,sc2[13]); sc2[13]=fma2(q3.y,k1.y,sc2[13]);
                sc2[14]=fma2(q3.x,k2.x,sc2[14]); sc2[14]=fma2(q3.y,k2.y,sc2[14]);
                sc2[15]=fma2(q3.x,k3.x,sc2[15]); sc2[15]=fma2(q3.y,k3.y,sc2[15]);
            }
            #pragma unroll
            for (int j = 0; j < 16; j++){
                float lo, hi; upk2(sc2[j], lo, hi);
                float v = lo + hi;
                #pragma unroll
                for (int o = 16; o; o >>= 1) v += __shfl_xor_sync(0xffffffffu, v, o);
                if (lane == j){
                    int hh = hgS*4 + (j >> 2), tt = tg4 + (j & 3);
                    p_s[hh*TB + tt] = v * SCALEF;
                }
            }
        }
        __syncthreads();

        // ---- parallel online softmax: 256 threads, one per (h,t) ----
        if (tid < 256){
            int h = tid >> 4, t = tid & 15;
            float mo = s_m[h];
            float sv = p_s[h*TB + t];
            float bm = sv;
            bm = fmaxf(bm, __shfl_xor_sync(0xffffffffu, bm, 1));
            bm = fmaxf(bm, __shfl_xor_sync(0xffffffffu, bm, 2));
            bm = fmaxf(bm, __shfl_xor_sync(0xffffffffu, bm, 4));
            bm = fmaxf(bm, __shfl_xor_sync(0xffffffffu, bm, 8));
            float mn = fmaxf(mo, bm);
            float p = __expf(sv - mn);
            float sum = p;
            sum += __shfl_xor_sync(0xffffffffu, sum, 1);
            sum += __shfl_xor_sync(0xffffffffu, sum, 2);
            sum += __shfl_xor_sync(0xffffffffu, sum, 4);
            sum += __shfl_xor_sync(0xffffffffu, sum, 8);
            p_s2[h*TB + t] = pk2(p, p);
            if (t == 0){
                float corr = __expf(mo - mn);
                s_c[h] = corr;
                s_l[h] = s_l[h]*corr + sum;
                s_m[h] = mn;
            }
        }
        __syncthreads();

        // ---- accumulate: 4 heads x 128 cols per warp, f32x2 ----
        {
            int hb = hgA*4;
            #pragma unroll
            for (int h = 0; h < 4; h++){
                float cv = s_c[hb+h];
                u64 cp = pk2(cv, cv);
                acc2[2*h]   = mul2(acc2[2*h], cp);
                acc2[2*h+1] = mul2(acc2[2*h+1], cp);
            }
            #pragma unroll
            for (int t = 0; t < TB; t++){
                ulonglong2 kv = *(const ulonglong2*)(kvc + t*KSTR + c0);
                u64 p0 = p_s2[(hb+0)*TB + t];
                u64 p1 = p_s2[(hb+1)*TB + t];
                u64 p2 = p_s2[(hb+2)*TB + t];
                u64 p3 = p_s2[(hb+3)*TB + t];
                acc2[0]=fma2(p0,kv.x,acc2[0]); acc2[1]=fma2(p0,kv.y,acc2[1]);
                acc2[2]=fma2(p1,kv.x,acc2[2]); acc2[3]=fma2(p1,kv.y,acc2[3]);
                acc2[4]=fma2(p2,kv.x,acc2[4]); acc2[5]=fma2(p2,kv.y,acc2[5]);
                acc2[6]=fma2(p3,kv.x,acc2[6]); acc2[7]=fma2(p3,kv.y,acc2[7]);
            }
        }

        if (doPre){
            #pragma unroll
            for (int k = 0; k < 4; k++){
                int i = tid + 512*k; int t = i/144, j = i%144;
                *(float4*)(kvn + t*KSTR + 4*j) = pre[k];
            }
            if (tid < 256){
                int i = tid + 2048; int t = i/144, j = i%144;
                *(float4*)(kvn + t*KSTR + 4*j) = pre[4];
            }
        }
        __syncthreads();
    }

    long base = ((long)(b*NCHUNK + chunk)*H + hgA*4)*KVLR + c0;
    #pragma unroll
    for (int h = 0; h < 4; h++){
        float ax, ay, az, aw;
        upk2(acc2[2*h], ax, ay);
        upk2(acc2[2*h+1], az, aw);
        *(float4*)(g_pout + base + (long)h*KVLR) = make_float4(ax, ay, az, aw);
    }
    if (tid < H){
        g_pm[(b*NCHUNK + chunk)*H + tid] = s_m[tid];
        g_pl[(b*NCHUNK + chunk)*H + tid] = s_l[tid];
    }
}

// ========== K6: combine split-softmax partials + V projection ==========
__global__ void k_reduce(const float* __restrict__ wkvb){
    int h = blockIdx.x, b = blockIdx.y, tid = threadIdx.x;
    __shared__ float sm_m[NCHUNK], sm_l[NCHUNK], wk[NCHUNK];
    __shared__ float so[KVLR];
    if (tid < NCHUNK){
        sm_m[tid] = g_pm[(b*NCHUNK + tid)*H + h];
        sm_l[tid] = g_pl[(b*NCHUNK + tid)*H + h];
    }
    __syncthreads();
    if (tid == 0){
        float M = -1e30f;
        for (int k = 0; k < NCHUNK; k++) M = fmaxf(M, sm_m[k]);
        float L = 0.f;
        for (int k = 0; k < NCHUNK; k++){ wk[k] = __expf(sm_m[k]-M)*sm_l[k]; L += wk[k]; }
        float inv = 1.f/L;
        for (int k = 0; k < NCHUNK; k++) wk[k] = __expf(sm_m[k]-M)*inv;
    }
    __syncthreads();
    float out = 0.f;
    #pragma unroll 4
    for (int k = 0; k < NCHUNK; k++)
        out += wk[k]*g_pout[((long)(b*NCHUNK + k)*H + h)*KVLR + tid];
    so[tid] = out;
    __syncthreads();
    int d = tid >> 2, part = tid & 3;
    const float* wr = wkvb + (long)(h*(DN+DV) + DN + d)*KVLR + part*128;
    const float* sp = so + part*128;
    float s = 0.f;
    #pragma unroll 8
    for (int c = 0; c < 128; c++) s += sp[c]*wr[c];
    s += __shfl_xor_sync(0xffffffffu, s, 1);
    s += __shfl_xor_sync(0xffffffffu, s, 2);
    if (part == 0) g_out2[(b*H + h)*DV + d] = s;
}

// ========== K7: y = out2 @ wo^T + wo_b ==========
__global__ void k_proj_o(const float* __restrict__ wo, const float* __restrict__ wob,
                         float* __restrict__ out){
    extern __shared__ float xs[];
    int tid = threadIdx.x;
    for (int i = tid; i < B*DIM; i += blockDim.x) xs[i] = g_out2[i];
    __syncthreads();
    int warp = tid >> 5, lane = tid & 31;
    int j = blockIdx.x * 8 + warp;
    const float* wr = wo + (long)j*DIM;
    float w[64];
    #pragma unroll
    for (int k = 0; k < 64; k++) w[k] = wr[lane + 32*k];
    float bias = wob[j];
    for (int b = 0; b < B; b++){
        const float* xb = xs + b*DIM;
        float s = 0.f;
        #pragma unroll
        for (int k = 0; k < 64; k++) s += w[k]*xb[lane + 32*k];
        #pragma unroll
        for (int o = 16; o; o >>= 1) s += __shfl_xor_sync(0xffffffffu, s, o);
        if (lane == 0) out[b*DIM + j] = s + bias;
    }
}

// ---------------- host launcher ----------------
extern "C" void kernel_launch(void* const* d_in, const int* in_sizes, int n_in,
                              void* d_out, int out_size){
    const float* x    = (const float*)d_in[0];
    const float* fcos = (const float*)d_in[2];
    const float* fsin = (const float*)d_in[3];
    const float* kvp  = (const float*)d_in[4];
    const float* pep  = (const float*)d_in[5];
    const float* wqa  = (const float*)d_in[6];
    const float* bqa  = (const float*)d_in[7];
    const float* qnw  = (const float*)d_in[8];
    const float* wqb  = (const float*)d_in[9];
    const float* bqb  = (const float*)d_in[10];
    const float* wkva = (const float*)d_in[11];
    const float* bkva = (const float*)d_in[12];
    const float* kvnw = (const float*)d_in[13];
    const float* wkvb = (const float*)d_in[14];
    const float* wo   = (const float*)d_in[15];
    const float* wob  = (const float*)d_in[16];
    float* out = (float*)d_out;

    const int SMEM_K1 = B*DIM*4;
    const int SMEM_K3 = B*QLR*4;
    const int SMEM_K5 = (H*DHEAD + 2*TB*KSTR + 256 + 512 + 48)*4;
    const int SMEM_K7 = B*DIM*4;
    cudaFuncSetAttribute(k_proj_a,  cudaFuncAttributeMaxDynamicSharedMemorySize, SMEM_K1);
    cudaFuncSetAttribute(k_proj_qb, cudaFuncAttributeMaxDynamicSharedMemorySize, SMEM_K3);
    cudaFuncSetAttribute(k_attn,    cudaFuncAttributeMaxDynamicSharedMemorySize, SMEM_K5);
    cudaFuncSetAttribute(k_proj_o,  cudaFuncAttributeMaxDynamicSharedMemorySize, SMEM_K7);

    k_proj_a<<<(QLR+KVLR+DR)/8, 256, SMEM_K1>>>(x, wqa, bqa, wkva, bkva);
    k_norm_rope<<<B, 512>>>(qnw, kvnw, fcos, fsin);
    k_proj_qb<<<(H*(DN+DR))/8, 256, SMEM_K3>>>(wqb, bqb);
    { dim3 g(H, 5); k_qfull<<<g, 512>>>(wkvb, fcos, fsin); }
    { dim3 g(NCHUNK, B); k_attn<<<g, 512, SMEM_K5>>>(kvp, pep); }
    { dim3 g(H, B); k_reduce<<<g, 512>>>(wkvb); }
    k_proj_o<<<DIM/8, 256, SMEM_K7>>>(wo, wob, out);
}

// round 9
// speedup vs baseline: 1.9396x; 1.1792x over previous
#include <cuda_runtime.h>
#include <cuda_bf16.h>
#include <cstdint>

// ---------------- problem constants ----------------
#define B 8
#define H 16
#define DIM 2048
#define QLR 1536
#define KVLR 512
#define DN 128
#define DR 64
#define DV 128
#define T_TOT 8192
#define T_PREFIX 8191
#define NCHUNK 128
#define CHUNK 64           // tokens per CTA in attention
#define DHEAD 576          // 512 + 64
#define KSTR 580           // padded fp32 row stride (mod 32 banks == 4 -> conflict-free frags)
#define SCALEF 0.07216878364870322f   // (DN+DR)^-0.5

typedef unsigned long long u64;

// ---------------- device scratch ----------------
__device__ float g_qa  [B*QLR];
__device__ float g_kvpe[B*(KVLR+DR)];
__device__ float g_qan [B*QLR];
__device__ float g_kvn [B*KVLR];
__device__ float g_pen [B*DR];
__device__ float g_q   [B*H*(DN+DR)];
__device__ float g_qfull[B*H*DHEAD];
__device__ float g_pm  [B*NCHUNK*H];
__device__ float g_pl  [B*NCHUNK*H];
__device__ float g_pout[B*NCHUNK*H*KVLR];    // 33.5 MB
__device__ float g_out2[B*H*DV];

// ---------------- packed f32x2 helpers ----------------
__device__ __forceinline__ u64 pk2(float lo, float hi){
    u64 r; asm("mov.b64 %0, {%1,%2};" : "=l"(r) : "f"(lo), "f"(hi)); return r;
}
__device__ __forceinline__ void upk2(u64 v, float& lo, float& hi){
    asm("mov.b64 {%0,%1}, %2;" : "=f"(lo), "=f"(hi) : "l"(v));
}
__device__ __forceinline__ u64 fma2(u64 a, u64 b, u64 c){
    u64 d; asm("fma.rn.f32x2 %0, %1, %2, %3;" : "=l"(d) : "l"(a), "l"(b), "l"(c)); return d;
}
__device__ __forceinline__ uint32_t tf32_of(float f){
    uint32_t r; asm("cvt.rna.tf32.f32 %0, %1;" : "=r"(r) : "f"(f)); return r;
}

// ========== K1: qa = x @ wq_a^T + b ; kvpe = x @ wkv_a^T + b ==========
__global__ void k_proj_a(const float* __restrict__ x,
                         const float* __restrict__ wqa, const float* __restrict__ bqa,
                         const float* __restrict__ wkva, const float* __restrict__ bkva){
    extern __shared__ float xs[];
    int tid = threadIdx.x;
    for (int i = tid; i < B*DIM; i += blockDim.x) xs[i] = x[i];
    __syncthreads();
    int warp = tid >> 5, lane = tid & 31;
    int r = blockIdx.x * 8 + warp;
    if (r >= QLR + KVLR + DR) return;
    const float* wrow; float bias;
    if (r < QLR) { wrow = wqa + (long)r*DIM; bias = bqa[r]; }
    else         { wrow = wkva + (long)(r-QLR)*DIM; bias = bkva[r-QLR]; }
    float w[64];
    #pragma unroll
    for (int k = 0; k < 64; k++) w[k] = wrow[lane + 32*k];
    for (int b = 0; b < B; b++){
        const float* xb = xs + b*DIM;
        float s = 0.f;
        #pragma unroll
        for (int k = 0; k < 64; k++) s += w[k]*xb[lane + 32*k];
        #pragma unroll
        for (int o = 16; o; o >>= 1) s += __shfl_xor_sync(0xffffffffu, s, o);
        if (lane == 0){
            if (r < QLR) g_qa[b*QLR + r] = s + bias;
            else         g_kvpe[b*(KVLR+DR) + (r-QLR)] = s + bias;
        }
    }
}

// ========== K2: RMS-norm qa and kv; rope k_pe ==========
__global__ void k_norm_rope(const float* __restrict__ qnw, const float* __restrict__ kvnw,
                            const float* __restrict__ fcos, const float* __restrict__ fsin){
    int b = blockIdx.x, tid = threadIdx.x;
    __shared__ float red[16];
    __shared__ float sq, skv;
    float s = 0.f;
    for (int i = tid; i < QLR; i += 512){ float v = g_qa[b*QLR+i]; s += v*v; }
    #pragma unroll
    for (int o = 16; o; o >>= 1) s += __shfl_xor_sync(0xffffffffu, s, o);
    if ((tid&31) == 0) red[tid>>5] = s;
    __syncthreads();
    if (tid == 0){ float t=0; for (int i=0;i<16;i++) t += red[i];
                   sq = rsqrtf(t*(1.f/QLR) + 1e-6f); }
    __syncthreads();
    float s2 = 0.f;
    { float v = (tid < KVLR) ? g_kvpe[b*(KVLR+DR)+tid] : 0.f; s2 = v*v; }
    #pragma unroll
    for (int o = 16; o; o >>= 1) s2 += __shfl_xor_sync(0xffffffffu, s2, o);
    if ((tid&31) == 0) red[tid>>5] = s2;
    __syncthreads();
    if (tid == 0){ float t=0; for (int i=0;i<16;i++) t += red[i];
                   skv = rsqrtf(t*(1.f/KVLR) + 1e-6f); }
    __syncthreads();
    for (int i = tid; i < QLR; i += 512) g_qan[b*QLR+i] = g_qa[b*QLR+i]*qnw[i]*sq;
    if (tid < KVLR) g_kvn[b*KVLR+tid] = g_kvpe[b*(KVLR+DR)+tid]*kvnw[tid]*skv;
    if (tid < DR){
        int i = tid >> 1;
        float xr = g_kvpe[b*(KVLR+DR)+KVLR+2*i];
        float xi = g_kvpe[b*(KVLR+DR)+KVLR+2*i+1];
        float c = fcos[i], sn = fsin[i];
        g_pen[b*DR+tid] = (tid&1) ? (xr*sn + xi*c) : (xr*c - xi*sn);
    }
}

// ========== K3: q = qa_n @ wq_b^T + b ==========
__global__ void k_proj_qb(const float* __restrict__ wqb, const float* __restrict__ bqb){
    extern __shared__ float qs[];
    int tid = threadIdx.x;
    for (int i = tid; i < B*QLR; i += blockDim.x) qs[i] = g_qan[i];
    __syncthreads();
    int warp = tid >> 5, lane = tid & 31;
    int r = blockIdx.x * 8 + warp;
    const float* wr = wqb + (long)r*QLR;
    float w[48];
    #pragma unroll
    for (int k = 0; k < 48; k++) w[k] = wr[lane + 32*k];
    float bias = bqb[r];
    for (int b = 0; b < B; b++){
        const float* xb = qs + b*QLR;
        float s = 0.f;
        #pragma unroll
        for (int k = 0; k < 48; k++) s += w[k]*xb[lane + 32*k];
        #pragma unroll
        for (int o = 16; o; o >>= 1) s += __shfl_xor_sync(0xffffffffu, s, o);
        if (lane == 0) g_q[b*(H*(DN+DR)) + r] = s + bias;
    }
}

// ========== K4: q_full = [q_nope @ wkv_b[:, :DN], rope(q_pe)] ==========
__global__ void k_qfull(const float* __restrict__ wkvb,
                        const float* __restrict__ fcos, const float* __restrict__ fsin){
    int h = blockIdx.x, part = blockIdx.y, tid = threadIdx.x;
    if (part < 4){
        __shared__ float qn[B][DN];
        __shared__ float red[4][B][129];
        for (int i = tid; i < B*DN; i += 512){ int b = i>>7, d = i&127;
            qn[b][d] = g_q[b*(H*(DN+DR)) + h*(DN+DR) + d]; }
        __syncthreads();
        int dg = tid >> 7, cc = tid & 127;
        int c = part*128 + cc;
        float acc[B];
        #pragma unroll
        for (int b = 0; b < B; b++) acc[b] = 0.f;
        const float* wp = wkvb + (long)(h*(DN+DV) + dg*32)*KVLR + c;
        #pragma unroll
        for (int ds = 0; ds < 32; ds += 4){
            float w0 = wp[(long)(ds+0)*KVLR];
            float w1 = wp[(long)(ds+1)*KVLR];
            float w2 = wp[(long)(ds+2)*KVLR];
            float w3 = wp[(long)(ds+3)*KVLR];
            #pragma unroll
            for (int b = 0; b < B; b++){
                float4 q = *(const float4*)(&qn[b][dg*32 + ds]);
                acc[b] += q.x*w0 + q.y*w1 + q.z*w2 + q.w*w3;
            }
        }
        #pragma unroll
        for (int b = 0; b < B; b++) red[dg][b][cc] = acc[b];
        __syncthreads();
        for (int i = tid; i < B*128; i += 512){
            int b = i >> 7, c2 = i & 127;
            float s = red[0][b][c2] + red[1][b][c2] + red[2][b][c2] + red[3][b][c2];
            g_qfull[(b*H + h)*DHEAD + part*128 + c2] = s;
        }
    } else {
        if (tid < DR){
            int i = tid >> 1;
            float c = fcos[i], sn = fsin[i];
            for (int b = 0; b < B; b++){
                float xr = g_q[b*(H*(DN+DR)) + h*(DN+DR) + DN + 2*i];
                float xi = g_q[b*(H*(DN+DR)) + h*(DN+DR) + DN + 2*i + 1];
                g_qfull[(b*H + h)*DHEAD + KVLR + tid] =
                    (tid&1) ? (xr*sn + xi*c) : (xr*c - xi*sn);
            }
        }
    }
}

// ---------- kv row gather (float4 index j over 144 = 128 kv + 16 pe) ----------
__device__ __forceinline__ float4 load_kv4(const float* __restrict__ kvp,
                                           const float* __restrict__ pep,
                                           int b, int tg, int j){
    if (tg == T_PREFIX){
        if (j < 128) return *(const float4*)(g_kvn + b*KVLR + 4*j);
        return *(const float4*)(g_pen + b*DR + 4*(j-128));
    }
    if (j < 128) return *(const float4*)(kvp + ((long)b*T_PREFIX + tg)*KVLR + 4*j);
    return *(const float4*)(pep + ((long)b*T_PREFIX + tg)*DR + 4*(j-128));
}

// ========== K5: attention — tf32 mma.sync scores + fp32 smem V accumulate ==========
// grid (128, 8), 512 threads. One 64-token chunk per CTA, one pass.
//
// smem layout (floats):
//   kvs [64][580] fp32 K-tile        offset 0       (37120 floats)
//   qs  [16][580] fp32 Q             offset 37120   (9280)
//   p_rawT [2][16][68] partial scores offset 46400  (2176)
//   p_pair [8][64][2] interleaved probs offset 48576 (1024)
#define SMF_KV 0
#define SMF_Q  37120
#define SMF_PR 46400
#define SMF_P2 48576
#define SM_TOTAL ((48576 + 1024)*4)   // 198400 bytes

__global__ void __launch_bounds__(512, 1) k_attn(const float* __restrict__ kvp,
                                                 const float* __restrict__ pep){
    extern __shared__ float smf[];
    float* kvs    = smf + SMF_KV;
    float* qs     = smf + SMF_Q;
    float* p_rawT = smf + SMF_PR;     // [2][16][68]
    float* p_pair = smf + SMF_P2;     // [8][64][2]
    int chunk = blockIdx.x, b = blockIdx.y, tid = threadIdx.x;
    int warp = tid >> 5, lane = tid & 31;
    int t0 = chunk*CHUNK;

    // ---- load Q fp32 (warp h -> head h) ----
    {
        int h = warp;
        const float* qr = g_qfull + (long)(b*H + h)*DHEAD;
        #pragma unroll
        for (int i = 0; i < 5; i++){
            int j = lane + 32*i;
            if (j < 144)
                *(float4*)(qs + h*KSTR + 4*j) = *(const float4*)(qr + 4*j);
        }
    }
    // ---- load K-tile fp32 (64 tokens x 576) ----
    for (int t = warp; t < CHUNK; t += 16){
        float* row = kvs + t*KSTR;
        #pragma unroll
        for (int i = 0; i < 5; i++){
            int j = lane + 32*i;
            if (j < 144)
                *(float4*)(row + 4*j) = load_kv4(kvp, pep, b, t0 + t, j);
        }
    }
    __syncthreads();

    // ---- scores: tf32 m16n8k8; 8 (m,n) tiles x 2-way k-split over 16 warps ----
    {
        int kh = warp >> 3;                   // k half: 0 or 1 (288 dims each)
        int tile = warp & 7;
        int tile_m = tile & 3, tile_n = tile >> 2;
        int l4 = lane >> 2, lm4 = lane & 3;
        const float* arow0 = kvs + (tile_m*16 + l4)*KSTR + lm4;
        const float* arow1 = arow0 + 8*KSTR;
        const float* brow  = qs  + (tile_n*8 + l4)*KSTR + lm4;
        float d0 = 0.f, d1 = 0.f, d2 = 0.f, d3 = 0.f;
        #pragma unroll
        for (int kc = 0; kc < 36; kc++){
            int k0 = kh*288 + kc*8;
            uint32_t a0 = tf32_of(arow0[k0]);
            uint32_t a1 = tf32_of(arow1[k0]);
            uint32_t a2 = tf32_of(arow0[k0+4]);
            uint32_t a3 = tf32_of(arow1[k0+4]);
            uint32_t b0 = tf32_of(brow[k0]);
            uint32_t b1 = tf32_of(brow[k0+4]);
            asm volatile("mma.sync.aligned.m16n8k8.row.col.f32.tf32.tf32.f32 "
                "{%0,%1,%2,%3}, {%4,%5,%6,%7}, {%8,%9}, {%0,%1,%2,%3};"
                : "+f"(d0),"+f"(d1),"+f"(d2),"+f"(d3)
                : "r"(a0),"r"(a1),"r"(a2),"r"(a3), "r"(b0),"r"(b1));
        }
        int r0 = tile_m*16 + l4;
        int h0 = tile_n*8 + 2*lm4;
        float* pr = p_rawT + kh*(16*68);
        pr[h0*68 + r0]         = d0;
        pr[(h0+1)*68 + r0]     = d1;
        pr[h0*68 + r0 + 8]     = d2;
        pr[(h0+1)*68 + r0 + 8] = d3;
    }
    __syncthreads();

    // ---- softmax per head over 64 tokens: warp h (sums the two k-halves) ----
    {
        int h = warp;
        const float* pr0 = p_rawT + h*68;
        const float* pr1 = p_rawT + 16*68 + h*68;
        float v0 = (pr0[lane]      + pr1[lane])      * SCALEF;
        float v1 = (pr0[lane + 32] + pr1[lane + 32]) * SCALEF;
        float m = fmaxf(v0, v1);
        #pragma unroll
        for (int o = 16; o; o >>= 1) m = fmaxf(m, __shfl_xor_sync(0xffffffffu, m, o));
        float p0 = __expf(v0 - m), p1 = __expf(v1 - m);
        float l = p0 + p1;
        #pragma unroll
        for (int o = 16; o; o >>= 1) l += __shfl_xor_sync(0xffffffffu, l, o);
        float* pb = p_pair + (h>>1)*128 + (h&1);
        pb[2*lane]        = p0;
        pb[2*(lane+32)]   = p1;
        if (lane == 0){
            g_pm[(b*NCHUNK + chunk)*H + h] = m;
            g_pl[(b*NCHUNK + chunk)*H + h] = l;
        }
    }
    __syncthreads();

    // ---- accumulate fp32 from smem: thread <-> kv column; 8 head-pair f32x2 accums ----
    {
        int c = tid;                          // 0..511
        const u64* pp = (const u64*)p_pair;   // [8][64]
        u64 acc[8];
        #pragma unroll
        for (int i = 0; i < 8; i++) acc[i] = 0ull;
        const float* kcol = kvs + c;
        #pragma unroll 4
        for (int t = 0; t < CHUNK; t++){
            float kvv = kcol[t*KSTR];
            u64 kv2 = pk2(kvv, kvv);
            #pragma unroll
            for (int hp = 0; hp < 8; hp++)
                acc[hp] = fma2(pp[hp*CHUNK + t], kv2, acc[hp]);
        }
        long basep = (long)(b*NCHUNK + chunk)*H*KVLR + c;
        #pragma unroll
        for (int hp = 0; hp < 8; hp++){
            float lo, hi; upk2(acc[hp], lo, hi);
            g_pout[basep + (long)(2*hp)*KVLR]   = lo;
            g_pout[basep + (long)(2*hp+1)*KVLR] = hi;
        }
    }
}

// ========== K6: combine split-softmax partials + V projection ==========
__global__ void k_reduce(const float* __restrict__ wkvb){
    int h = blockIdx.x, b = blockIdx.y, tid = threadIdx.x;
    __shared__ float sm_m[NCHUNK], sm_l[NCHUNK], wk[NCHUNK];
    __shared__ float so[KVLR];
    if (tid < NCHUNK){
        sm_m[tid] = g_pm[(b*NCHUNK + tid)*H + h];
        sm_l[tid] = g_pl[(b*NCHUNK + tid)*H + h];
    }
    __syncthreads();
    if (tid < 32){
        float mv = (tid < NCHUNK) ? sm_m[tid] : -1e30f;
        float m2 = (tid+32 < NCHUNK) ? sm_m[tid+32] : -1e30f;
        float m3 = (tid+64 < NCHUNK) ? sm_m[tid+64] : -1e30f;
        float m4 = (tid+96 < NCHUNK) ? sm_m[tid+96] : -1e30f;
        float M = fmaxf(fmaxf(mv,m2), fmaxf(m3,m4));
        #pragma unroll
        for (int o = 16; o; o >>= 1) M = fmaxf(M, __shfl_xor_sync(0xffffffffu, M, o));
        float e1 = __expf(mv - M), e2 = __expf(m2 - M);
        float e3 = __expf(m3 - M), e4 = __expf(m4 - M);
        float L = e1*sm_l[tid] + e2*sm_l[tid+32] + e3*sm_l[tid+64] + e4*sm_l[tid+96];
        #pragma unroll
        for (int o = 16; o; o >>= 1) L += __shfl_xor_sync(0xffffffffu, L, o);
        float inv = 1.f/L;
        wk[tid]    = e1*inv;
        wk[tid+32] = e2*inv;
        wk[tid+64] = e3*inv;
        wk[tid+96] = e4*inv;
    }
    __syncthreads();
    float out = 0.f;
    #pragma unroll 4
    for (int k = 0; k < NCHUNK; k++)
        out += wk[k]*g_pout[((long)(b*NCHUNK + k)*H + h)*KVLR + tid];
    so[tid] = out;
    __syncthreads();
    int d = tid >> 2, part = tid & 3;
    const float* wr = wkvb + (long)(h*(DN+DV) + DN + d)*KVLR + part*128;
    const float* sp = so + part*128;
    float s = 0.f;
    #pragma unroll 8
    for (int c = 0; c < 128; c++) s += sp[c]*wr[c];
    s += __shfl_xor_sync(0xffffffffu, s, 1);
    s += __shfl_xor_sync(0xffffffffu, s, 2);
    if (part == 0) g_out2[(b*H + h)*DV + d] = s;
}

// ========== K7: y = out2 @ wo^T + wo_b ==========
__global__ void k_proj_o(const float* __restrict__ wo, const float* __restrict__ wob,
                         float* __restrict__ out){
    extern __shared__ float xs[];
    int tid = threadIdx.x;
    for (int i = tid; i < B*DIM; i += blockDim.x) xs[i] = g_out2[i];
    __syncthreads();
    int warp = tid >> 5, lane = tid & 31;
    int j = blockIdx.x * 8 + warp;
    const float* wr = wo + (long)j*DIM;
    float w[64];
    #pragma unroll
    for (int k = 0; k < 64; k++) w[k] = wr[lane + 32*k];
    float bias = wob[j];
    for (int b = 0; b < B; b++){
        const float* xb = xs + b*DIM;
        float s = 0.f;
        #pragma unroll
        for (int k = 0; k < 64; k++) s += w[k]*xb[lane + 32*k];
        #pragma unroll
        for (int o = 16; o; o >>= 1) s += __shfl_xor_sync(0xffffffffu, s, o);
        if (lane == 0) out[b*DIM + j] = s + bias;
    }
}

// ---------------- host launcher ----------------
extern "C" void kernel_launch(void* const* d_in, const int* in_sizes, int n_in,
                              void* d_out, int out_size){
    const float* x    = (const float*)d_in[0];
    const float* fcos = (const float*)d_in[2];
    const float* fsin = (const float*)d_in[3];
    const float* kvp  = (const float*)d_in[4];
    const float* pep  = (const float*)d_in[5];
    const float* wqa  = (const float*)d_in[6];
    const float* bqa  = (const float*)d_in[7];
    const float* qnw  = (const float*)d_in[8];
    const float* wqb  = (const float*)d_in[9];
    const float* bqb  = (const float*)d_in[10];
    const float* wkva = (const float*)d_in[11];
    const float* bkva = (const float*)d_in[12];
    const float* kvnw = (const float*)d_in[13];
    const float* wkvb = (const float*)d_in[14];
    const float* wo   = (const float*)d_in[15];
    const float* wob  = (const float*)d_in[16];
    float* out = (float*)d_out;

    const int SMEM_K1 = B*DIM*4;
    const int SMEM_K3 = B*QLR*4;
    const int SMEM_K7 = B*DIM*4;
    cudaFuncSetAttribute(k_proj_a,  cudaFuncAttributeMaxDynamicSharedMemorySize, SMEM_K1);
    cudaFuncSetAttribute(k_proj_qb, cudaFuncAttributeMaxDynamicSharedMemorySize, SMEM_K3);
    cudaFuncSetAttribute(k_attn,    cudaFuncAttributeMaxDynamicSharedMemorySize, SM_TOTAL);
    cudaFuncSetAttribute(k_proj_o,  cudaFuncAttributeMaxDynamicSharedMemorySize, SMEM_K7);

    k_proj_a<<<(QLR+KVLR+DR)/8, 256, SMEM_K1>>>(x, wqa, bqa, wkva, bkva);
    k_norm_rope<<<B, 512>>>(qnw, kvnw, fcos, fsin);
    k_proj_qb<<<(H*(DN+DR))/8, 256, SMEM_K3>>>(wqb, bqb);
    { dim3 g(H, 5); k_qfull<<<g, 512>>>(wkvb, fcos, fsin); }
    { dim3 g(NCHUNK, B); k_attn<<<g, 512, SM_TOTAL>>>(kvp, pep); }
    { dim3 g(H, B); k_reduce<<<g, 512>>>(wkvb); }
    k_proj_o<<<DIM/8, 256, SMEM_K7>>>(wo, wob, out);
}

// round 10
// speedup vs baseline: 2.7917x; 1.4393x over previous
#include <cuda_runtime.h>
#include <cuda_bf16.h>
#include <cstdint>

// ---------------- problem constants ----------------
#define B 8
#define H 16
#define DIM 2048
#define QLR 1536
#define KVLR 512
#define DN 128
#define DR 64
#define DV 128
#define T_TOT 8192
#define T_PREFIX 8191
#define NCHUNK 16          // one partial per CTA
#define NCPC 16            // chunks per CTA
#define CHUNK 32           // tokens per chunk
#define DHEAD 576
#define KSTR 580           // fp32 row stride (≡4 mod 32 banks -> conflict-free frags)
#define PSTR 36            // probs row stride (≡4 mod 32)
#define SCALEF 0.07216878364870322f

typedef unsigned long long u64;

// ---------------- device scratch ----------------
__device__ float g_qa  [B*QLR];
__device__ float g_kvpe[B*(KVLR+DR)];
__device__ float g_qan [B*QLR];
__device__ float g_kvn [B*KVLR];
__device__ float g_pen [B*DR];
__device__ float g_q   [B*H*(DN+DR)];
__device__ float g_qfull[B*H*DHEAD];
__device__ float g_pm  [B*NCHUNK*H];
__device__ float g_pl  [B*NCHUNK*H];
__device__ float g_pout[B*NCHUNK*H*KVLR];    // 4.2 MB
__device__ float g_out2[B*H*DV];

__device__ __forceinline__ uint32_t tf32_of(float f){
    uint32_t r; asm("cvt.rna.tf32.f32 %0, %1;" : "=r"(r) : "f"(f)); return r;
}
__device__ __forceinline__ uint32_t smem_u32(const void* p){
    uint32_t a;
    asm("{ .reg .u64 t; cvta.to.shared.u64 t, %1; cvt.u32.u64 %0, t; }" : "=r"(a) : "l"(p));
    return a;
}

// ========== K1: qa = x @ wq_a^T + b ; kvpe = x @ wkv_a^T + b ==========
__global__ void k_proj_a(const float* __restrict__ x,
                         const float* __restrict__ wqa, const float* __restrict__ bqa,
                         const float* __restrict__ wkva, const float* __restrict__ bkva){
    extern __shared__ float xs[];
    int tid = threadIdx.x;
    for (int i = tid; i < B*DIM; i += blockDim.x) xs[i] = x[i];
    __syncthreads();
    int warp = tid >> 5, lane = tid & 31;
    int r = blockIdx.x * 8 + warp;
    if (r >= QLR + KVLR + DR) return;
    const float* wrow; float bias;
    if (r < QLR) { wrow = wqa + (long)r*DIM; bias = bqa[r]; }
    else         { wrow = wkva + (long)(r-QLR)*DIM; bias = bkva[r-QLR]; }
    float w[64];
    #pragma unroll
    for (int k = 0; k < 64; k++) w[k] = wrow[lane + 32*k];
    for (int b = 0; b < B; b++){
        const float* xb = xs + b*DIM;
        float s = 0.f;
        #pragma unroll
        for (int k = 0; k < 64; k++) s += w[k]*xb[lane + 32*k];
        #pragma unroll
        for (int o = 16; o; o >>= 1) s += __shfl_xor_sync(0xffffffffu, s, o);
        if (lane == 0){
            if (r < QLR) g_qa[b*QLR + r] = s + bias;
            else         g_kvpe[b*(KVLR+DR) + (r-QLR)] = s + bias;
        }
    }
}

// ========== K2: RMS-norm qa and kv; rope k_pe ==========
__global__ void k_norm_rope(const float* __restrict__ qnw, const float* __restrict__ kvnw,
                            const float* __restrict__ fcos, const float* __restrict__ fsin){
    int b = blockIdx.x, tid = threadIdx.x;
    __shared__ float red[16];
    __shared__ float sq, skv;
    float s = 0.f;
    for (int i = tid; i < QLR; i += 512){ float v = g_qa[b*QLR+i]; s += v*v; }
    #pragma unroll
    for (int o = 16; o; o >>= 1) s += __shfl_xor_sync(0xffffffffu, s, o);
    if ((tid&31) == 0) red[tid>>5] = s;
    __syncthreads();
    if (tid == 0){ float t=0; for (int i=0;i<16;i++) t += red[i];
                   sq = rsqrtf(t*(1.f/QLR) + 1e-6f); }
    __syncthreads();
    float s2 = 0.f;
    { float v = (tid < KVLR) ? g_kvpe[b*(KVLR+DR)+tid] : 0.f; s2 = v*v; }
    #pragma unroll
    for (int o = 16; o; o >>= 1) s2 += __shfl_xor_sync(0xffffffffu, s2, o);
    if ((tid&31) == 0) red[tid>>5] = s2;
    __syncthreads();
    if (tid == 0){ float t=0; for (int i=0;i<16;i++) t += red[i];
                   skv = rsqrtf(t*(1.f/KVLR) + 1e-6f); }
    __syncthreads();
    for (int i = tid; i < QLR; i += 512) g_qan[b*QLR+i] = g_qa[b*QLR+i]*qnw[i]*sq;
    if (tid < KVLR) g_kvn[b*KVLR+tid] = g_kvpe[b*(KVLR+DR)+tid]*kvnw[tid]*skv;
    if (tid < DR){
        int i = tid >> 1;
        float xr = g_kvpe[b*(KVLR+DR)+KVLR+2*i];
        float xi = g_kvpe[b*(KVLR+DR)+KVLR+2*i+1];
        float c = fcos[i], sn = fsin[i];
        g_pen[b*DR+tid] = (tid&1) ? (xr*sn + xi*c) : (xr*c - xi*sn);
    }
}

// ========== K3: q = qa_n @ wq_b^T + b ==========
__global__ void k_proj_qb(const float* __restrict__ wqb, const float* __restrict__ bqb){
    extern __shared__ float qs[];
    int tid = threadIdx.x;
    for (int i = tid; i < B*QLR; i += blockDim.x) qs[i] = g_qan[i];
    __syncthreads();
    int warp = tid >> 5, lane = tid & 31;
    int r = blockIdx.x * 8 + warp;
    const float* wr = wqb + (long)r*QLR;
    float w[48];
    #pragma unroll
    for (int k = 0; k < 48; k++) w[k] = wr[lane + 32*k];
    float bias = bqb[r];
    for (int b = 0; b < B; b++){
        const float* xb = qs + b*QLR;
        float s = 0.f;
        #pragma unroll
        for (int k = 0; k < 48; k++) s += w[k]*xb[lane + 32*k];
        #pragma unroll
        for (int o = 16; o; o >>= 1) s += __shfl_xor_sync(0xffffffffu, s, o);
        if (lane == 0) g_q[b*(H*(DN+DR)) + r] = s + bias;
    }
}

// ========== K4: q_full = [q_nope @ wkv_b[:, :DN], rope(q_pe)] ==========
__global__ void k_qfull(const float* __restrict__ wkvb,
                        const float* __restrict__ fcos, const float* __restrict__ fsin){
    int h = blockIdx.x, part = blockIdx.y, tid = threadIdx.x;
    if (part < 4){
        __shared__ float qn[B][DN];
        __shared__ float red[4][B][129];
        for (int i = tid; i < B*DN; i += 512){ int b = i>>7, d = i&127;
            qn[b][d] = g_q[b*(H*(DN+DR)) + h*(DN+DR) + d]; }
        __syncthreads();
        int dg = tid >> 7, cc = tid & 127;
        int c = part*128 + cc;
        float acc[B];
        #pragma unroll
        for (int b = 0; b < B; b++) acc[b] = 0.f;
        const float* wp = wkvb + (long)(h*(DN+DV) + dg*32)*KVLR + c;
        #pragma unroll
        for (int ds = 0; ds < 32; ds += 4){
            float w0 = wp[(long)(ds+0)*KVLR];
            float w1 = wp[(long)(ds+1)*KVLR];
            float w2 = wp[(long)(ds+2)*KVLR];
            float w3 = wp[(long)(ds+3)*KVLR];
            #pragma unroll
            for (int b = 0; b < B; b++){
                float4 q = *(const float4*)(&qn[b][dg*32 + ds]);
                acc[b] += q.x*w0 + q.y*w1 + q.z*w2 + q.w*w3;
            }
        }
        #pragma unroll
        for (int b = 0; b < B; b++) red[dg][b][cc] = acc[b];
        __syncthreads();
        for (int i = tid; i < B*128; i += 512){
            int b = i >> 7, c2 = i & 127;
            float s = red[0][b][c2] + red[1][b][c2] + red[2][b][c2] + red[3][b][c2];
            g_qfull[(b*H + h)*DHEAD + part*128 + c2] = s;
        }
    } else {
        if (tid < DR){
            int i = tid >> 1;
            float c = fcos[i], sn = fsin[i];
            for (int b = 0; b < B; b++){
                float xr = g_q[b*(H*(DN+DR)) + h*(DN+DR) + DN + 2*i];
                float xi = g_q[b*(H*(DN+DR)) + h*(DN+DR) + DN + 2*i + 1];
                g_qfull[(b*H + h)*DHEAD + KVLR + tid] =
                    (tid&1) ? (xr*sn + xi*c) : (xr*c - xi*sn);
            }
        }
    }
}

// ========== K5: persistent split-K attention ==========
// grid (16, 8), 512 threads. Each CTA: 16 chunks x 32 tokens, online softmax,
// cp.async double-buffered kv, tf32 MMA for BOTH scores and P@KV.
//
// smem floats:
//   kv0 [32*580] 18560 | kv1 [32*580] | qs [16*580] 9280
//   pr  [4][16][36] 2304 | ps [16][36] 576 | s_c [16]
#define SMF_KV0 0
#define SMF_KV1 18560
#define SMF_Q   37120
#define SMF_PR  46400
#define SMF_PS  48704
#define SMF_SC  49280
#define SM_TOTAL ((49280 + 16)*4)   // 197184 bytes

__device__ __forceinline__ void issue_chunk(
    const float* __restrict__ kvp, const float* __restrict__ pep,
    int b, int t0, uint32_t dstbase, const int* tk, const int* jk){
    #pragma unroll
    for (int k = 0; k < 9; k++){
        int tg = t0 + tk[k];
        int j = jk[k];
        const char* src;
        if (tg == T_PREFIX)
            src = (j < 128) ? (const char*)(g_kvn + b*KVLR) + j*16
                            : (const char*)(g_pen + b*DR) + (j-128)*16;
        else
            src = (j < 128) ? (const char*)(kvp + ((long)b*T_PREFIX + tg)*KVLR) + j*16
                            : (const char*)(pep + ((long)b*T_PREFIX + tg)*DR) + (j-128)*16;
        uint32_t dst = dstbase + (uint32_t)(tk[k]*2320 + j*16);
        asm volatile("cp.async.cg.shared.global [%0], [%1], 16;" :: "r"(dst), "l"(src));
    }
    asm volatile("cp.async.commit_group;" ::: "memory");
}

__global__ void __launch_bounds__(512, 1) k_attn(const float* __restrict__ kvp,
                                                 const float* __restrict__ pep){
    extern __shared__ float smf[];
    float* qs  = smf + SMF_Q;
    float* pr  = smf + SMF_PR;    // [4][16][36]
    float* ps  = smf + SMF_PS;    // [16][36]
    float* s_c = smf + SMF_SC;    // [16]
    int g = blockIdx.x, b = blockIdx.y, tid = threadIdx.x;
    int warp = tid >> 5, lane = tid & 31;
    int l4 = lane >> 2, lm4 = lane & 3;
    uint32_t sb = smem_u32(smf);

    // per-thread cp.async index precompute (9 x 16B ops per thread per chunk)
    int tk[9], jk[9];
    #pragma unroll
    for (int k = 0; k < 9; k++){ int idx = tid + 512*k; tk[k] = idx/144; jk[k] = idx%144; }

    // kick off chunk 0
    issue_chunk(kvp, pep, b, g*NCPC*CHUNK, sb + SMF_KV0*4, tk, jk);

    // load Q (warp h -> head h) while chunk 0 streams
    {
        int h = warp;
        const float* qr = g_qfull + (long)(b*H + h)*DHEAD;
        #pragma unroll
        for (int i = 0; i < 5; i++){
            int j = lane + 32*i;
            if (j < 144)
                *(float4*)(qs + h*KSTR + 4*j) = *(const float4*)(qr + 4*j);
        }
    }

    float m_run = -1e30f, l_run = 0.f;
    float acc[4][4];
    #pragma unroll
    for (int nt = 0; nt < 4; nt++)
        #pragma unroll
        for (int j = 0; j < 4; j++) acc[nt][j] = 0.f;

    for (int i = 0; i < NCPC; i++){
        if (i + 1 < NCPC){
            issue_chunk(kvp, pep, b, (g*NCPC + i + 1)*CHUNK,
                        sb + (((i+1)&1) ? SMF_KV1 : SMF_KV0)*4, tk, jk);
            asm volatile("cp.async.wait_group 1;" ::: "memory");
        } else {
            asm volatile("cp.async.wait_group 0;" ::: "memory");
        }
        __syncthreads();
        const float* kvs = smf + ((i&1) ? SMF_KV1 : SMF_KV0);

        // ---- scores: 2 m-tiles x 2 n-tiles x 4-way k-split (144 dims each) ----
        {
            int tile_m = warp & 1, tile_n = (warp >> 1) & 1, kh = warp >> 2;
            const float* arow0 = kvs + (tile_m*16 + l4)*KSTR + lm4;
            const float* arow1 = arow0 + 8*KSTR;
            const float* brow  = qs  + (tile_n*8 + l4)*KSTR + lm4;
            float d0 = 0.f, d1 = 0.f, d2 = 0.f, d3 = 0.f;
            #pragma unroll
            for (int kc = 0; kc < 18; kc++){
                int k0 = kh*144 + kc*8;
                uint32_t a0 = tf32_of(arow0[k0]);
                uint32_t a1 = tf32_of(arow1[k0]);
                uint32_t a2 = tf32_of(arow0[k0+4]);
                uint32_t a3 = tf32_of(arow1[k0+4]);
                uint32_t b0 = tf32_of(brow[k0]);
                uint32_t b1 = tf32_of(brow[k0+4]);
                asm volatile("mma.sync.aligned.m16n8k8.row.col.f32.tf32.tf32.f32 "
                    "{%0,%1,%2,%3}, {%4,%5,%6,%7}, {%8,%9}, {%0,%1,%2,%3};"
                    : "+f"(d0),"+f"(d1),"+f"(d2),"+f"(d3)
                    : "r"(a0),"r"(a1),"r"(a2),"r"(a3), "r"(b0),"r"(b1));
            }
            int r0 = tile_m*16 + l4;
            int h0 = tile_n*8 + 2*lm4;
            pr[kh*576 + h0*PSTR + r0]           = d0;
            pr[kh*576 + (h0+1)*PSTR + r0]       = d1;
            pr[kh*576 + h0*PSTR + r0 + 8]       = d2;
            pr[kh*576 + (h0+1)*PSTR + r0 + 8]   = d3;
        }
        __syncthreads();

        // ---- online softmax: warp h, one token per lane ----
        {
            int h = warp;
            float v = (pr[h*PSTR + lane] + pr[576 + h*PSTR + lane]
                     + pr[1152 + h*PSTR + lane] + pr[1728 + h*PSTR + lane]) * SCALEF;
            float bm = v;
            #pragma unroll
            for (int o = 16; o; o >>= 1) bm = fmaxf(bm, __shfl_xor_sync(0xffffffffu, bm, o));
            float mn = fmaxf(m_run, bm);
            float corr = __expf(m_run - mn);
            float p = __expf(v - mn);
            float l = p;
            #pragma unroll
            for (int o = 16; o; o >>= 1) l += __shfl_xor_sync(0xffffffffu, l, o);
            l_run = l_run*corr + l;
            m_run = mn;
            ps[h*PSTR + lane] = p;
            if (lane == 0) s_c[h] = corr;
        }
        __syncthreads();

        // ---- accumulate via tf32 MMA: out[16h][32c per warp] += P @ KV ----
        {
            int n0 = warp*32;
            float corr0 = s_c[l4], corr1 = s_c[l4+8];
            #pragma unroll
            for (int nt = 0; nt < 4; nt++){
                acc[nt][0] *= corr0; acc[nt][1] *= corr0;
                acc[nt][2] *= corr1; acc[nt][3] *= corr1;
            }
            #pragma unroll
            for (int ks = 0; ks < 4; ks++){
                int k0 = ks*8;
                uint32_t a0 = tf32_of(ps[l4*PSTR + k0 + lm4]);
                uint32_t a1 = tf32_of(ps[(l4+8)*PSTR + k0 + lm4]);
                uint32_t a2 = tf32_of(ps[l4*PSTR + k0 + 4 + lm4]);
                uint32_t a3 = tf32_of(ps[(l4+8)*PSTR + k0 + 4 + lm4]);
                #pragma unroll
                for (int nt = 0; nt < 4; nt++){
                    int cn = n0 + nt*8 + l4;
                    uint32_t b0 = tf32_of(kvs[(k0 + lm4)*KSTR + cn]);
                    uint32_t b1 = tf32_of(kvs[(k0 + 4 + lm4)*KSTR + cn]);
                    asm volatile("mma.sync.aligned.m16n8k8.row.col.f32.tf32.tf32.f32 "
                        "{%0,%1,%2,%3}, {%4,%5,%6,%7}, {%8,%9}, {%0,%1,%2,%3};"
                        : "+f"(acc[nt][0]),"+f"(acc[nt][1]),"+f"(acc[nt][2]),"+f"(acc[nt][3])
                        : "r"(a0),"r"(a1),"r"(a2),"r"(a3), "r"(b0),"r"(b1));
                }
            }
        }
        __syncthreads();   // protect kvs (next issue) and ps/s_c (next softmax)
    }

    // ---- writeout: one partial per CTA ----
    if (lane == 0){
        g_pm[(b*NCHUNK + g)*H + warp] = m_run;
        g_pl[(b*NCHUNK + g)*H + warp] = l_run;
    }
    {
        int n0 = warp*32;
        long base0 = ((long)(b*NCHUNK + g)*H + l4)*KVLR;
        long base1 = ((long)(b*NCHUNK + g)*H + l4 + 8)*KVLR;
        #pragma unroll
        for (int nt = 0; nt < 4; nt++){
            int c = n0 + nt*8 + 2*lm4;
            *(float2*)(g_pout + base0 + c) = make_float2(acc[nt][0], acc[nt][1]);
            *(float2*)(g_pout + base1 + c) = make_float2(acc[nt][2], acc[nt][3]);
        }
    }
}

// ========== K6: combine split-softmax partials + V projection ==========
__global__ void k_reduce(const float* __restrict__ wkvb){
    int h = blockIdx.x, b = blockIdx.y, tid = threadIdx.x;
    __shared__ float sm_m[NCHUNK], sm_l[NCHUNK], wk[NCHUNK];
    __shared__ float so[KVLR];
    if (tid < NCHUNK){
        sm_m[tid] = g_pm[(b*NCHUNK + tid)*H + h];
        sm_l[tid] = g_pl[(b*NCHUNK + tid)*H + h];
    }
    __syncthreads();
    if (tid < 32){
        float mv = (tid < NCHUNK) ? sm_m[tid] : -1e30f;
        float M = mv;
        #pragma unroll
        for (int o = 16; o; o >>= 1) M = fmaxf(M, __shfl_xor_sync(0xffffffffu, M, o));
        float e = __expf(mv - M);
        float L = (tid < NCHUNK) ? e*sm_l[tid] : 0.f;
        #pragma unroll
        for (int o = 16; o; o >>= 1) L += __shfl_xor_sync(0xffffffffu, L, o);
        if (tid < NCHUNK) wk[tid] = e / L;
    }
    __syncthreads();
    float out = 0.f;
    #pragma unroll
    for (int k = 0; k < NCHUNK; k++)
        out += wk[k]*g_pout[((long)(b*NCHUNK + k)*H + h)*KVLR + tid];
    so[tid] = out;
    __syncthreads();
    int d = tid >> 2, part = tid & 3;
    const float* wr = wkvb + (long)(h*(DN+DV) + DN + d)*KVLR + part*128;
    const float* sp = so + part*128;
    float s = 0.f;
    #pragma unroll 8
    for (int c = 0; c < 128; c++) s += sp[c]*wr[c];
    s += __shfl_xor_sync(0xffffffffu, s, 1);
    s += __shfl_xor_sync(0xffffffffu, s, 2);
    if (part == 0) g_out2[(b*H + h)*DV + d] = s;
}

// ========== K7: y = out2 @ wo^T + wo_b ==========
__global__ void k_proj_o(const float* __restrict__ wo, const float* __restrict__ wob,
                         float* __restrict__ out){
    extern __shared__ float xs[];
    int tid = threadIdx.x;
    for (int i = tid; i < B*DIM; i += blockDim.x) xs[i] = g_out2[i];
    __syncthreads();
    int warp = tid >> 5, lane = tid & 31;
    int j = blockIdx.x * 8 + warp;
    const float* wr = wo + (long)j*DIM;
    float w[64];
    #pragma unroll
    for (int k = 0; k < 64; k++) w[k] = wr[lane + 32*k];
    float bias = wob[j];
    for (int b = 0; b < B; b++){
        const float* xb = xs + b*DIM;
        float s = 0.f;
        #pragma unroll
        for (int k = 0; k < 64; k++) s += w[k]*xb[lane + 32*k];
        #pragma unroll
        for (int o = 16; o; o >>= 1) s += __shfl_xor_sync(0xffffffffu, s, o);
        if (lane == 0) out[b*DIM + j] = s + bias;
    }
}

// ---------------- host launcher ----------------
extern "C" void kernel_launch(void* const* d_in, const int* in_sizes, int n_in,
                              void* d_out, int out_size){
    const float* x    = (const float*)d_in[0];
    const float* fcos = (const float*)d_in[2];
    const float* fsin = (const float*)d_in[3];
    const float* kvp  = (const float*)d_in[4];
    const float* pep  = (const float*)d_in[5];
    const float* wqa  = (const float*)d_in[6];
    const float* bqa  = (const float*)d_in[7];
    const float* qnw  = (const float*)d_in[8];
    const float* wqb  = (const float*)d_in[9];
    const float* bqb  = (const float*)d_in[10];
    const float* wkva = (const float*)d_in[11];
    const float* bkva = (const float*)d_in[12];
    const float* kvnw = (const float*)d_in[13];
    const float* wkvb = (const float*)d_in[14];
    const float* wo   = (const float*)d_in[15];
    const float* wob  = (const float*)d_in[16];
    float* out = (float*)d_out;

    const int SMEM_K1 = B*DIM*4;
    const int SMEM_K3 = B*QLR*4;
    const int SMEM_K7 = B*DIM*4;
    cudaFuncSetAttribute(k_proj_a,  cudaFuncAttributeMaxDynamicSharedMemorySize, SMEM_K1);
    cudaFuncSetAttribute(k_proj_qb, cudaFuncAttributeMaxDynamicSharedMemorySize, SMEM_K3);
    cudaFuncSetAttribute(k_attn,    cudaFuncAttributeMaxDynamicSharedMemorySize, SM_TOTAL);
    cudaFuncSetAttribute(k_proj_o,  cudaFuncAttributeMaxDynamicSharedMemorySize, SMEM_K7);

    k_proj_a<<<(QLR+KVLR+DR)/8, 256, SMEM_K1>>>(x, wqa, bqa, wkva, bkva);
    k_norm_rope<<<B, 512>>>(qnw, kvnw, fcos, fsin);
    k_proj_qb<<<(H*(DN+DR))/8, 256, SMEM_K3>>>(wqb, bqb);
    { dim3 g(H, 5); k_qfull<<<g, 512>>>(wkvb, fcos, fsin); }
    { dim3 g(NCHUNK, B); k_attn<<<g, 512, SM_TOTAL>>>(kvp, pep); }
    { dim3 g(H, B); k_reduce<<<g, 512>>>(wkvb); }
    k_proj_o<<<DIM/8, 256, SMEM_K7>>>(wo, wob, out);
}

// round 11
// speedup vs baseline: 2.9342x; 1.0511x over previous
#include <cuda_runtime.h>
#include <cuda_bf16.h>
#include <cstdint>

// ---------------- problem constants ----------------
#define B 8
#define H 16
#define DIM 2048
#define QLR 1536
#define KVLR 512
#define DN 128
#define DR 64
#define DV 128
#define T_TOT 8192
#define T_PREFIX 8191
#define NCHUNK 16          // one partial per CTA
#define NCPC 16            // chunks per CTA
#define CHUNK 32           // tokens per chunk
#define DHEAD 576
#define KSTR 580           // fp32 row stride (≡4 mod 32 banks -> conflict-free frags)
#define PSTR 36            // probs row stride (≡4 mod 32)
#define SCALEF 0.07216878364870322f

typedef unsigned long long u64;

// ---------------- device scratch ----------------
__device__ float g_qa  [B*QLR];
__device__ float g_kvpe[B*(KVLR+DR)];
__device__ float g_qan [B*QLR];
__device__ float g_kvn [B*KVLR];
__device__ float g_pen [B*DR];
__device__ float g_q   [B*H*(DN+DR)];
__device__ float g_qfull[B*H*DHEAD];
__device__ float g_pm  [B*NCHUNK*H];
__device__ float g_pl  [B*NCHUNK*H];
__device__ float g_pout[B*NCHUNK*H*KVLR];    // 4.2 MB
__device__ float g_out2[B*H*DV];

__device__ __forceinline__ uint32_t tf32_of(float f){
    uint32_t r; asm("cvt.rna.tf32.f32 %0, %1;" : "=r"(r) : "f"(f)); return r;
}
__device__ __forceinline__ uint32_t smem_u32(const void* p){
    uint32_t a;
    asm("{ .reg .u64 t; cvta.to.shared.u64 t, %1; cvt.u32.u64 %0, t; }" : "=r"(a) : "l"(p));
    return a;
}

// ========== K1: qa = x @ wq_a^T + b ; kvpe = x @ wkv_a^T + b ==========
__global__ void k_proj_a(const float* __restrict__ x,
                         const float* __restrict__ wqa, const float* __restrict__ bqa,
                         const float* __restrict__ wkva, const float* __restrict__ bkva){
    extern __shared__ float xs[];
    int tid = threadIdx.x;
    for (int i = tid; i < B*DIM; i += blockDim.x) xs[i] = x[i];
    __syncthreads();
    int warp = tid >> 5, lane = tid & 31;
    int r = blockIdx.x * 8 + warp;
    if (r >= QLR + KVLR + DR) return;
    const float* wrow; float bias;
    if (r < QLR) { wrow = wqa + (long)r*DIM; bias = bqa[r]; }
    else         { wrow = wkva + (long)(r-QLR)*DIM; bias = bkva[r-QLR]; }
    float w[64];
    #pragma unroll
    for (int k = 0; k < 64; k++) w[k] = wrow[lane + 32*k];
    for (int b = 0; b < B; b++){
        const float* xb = xs + b*DIM;
        float s = 0.f;
        #pragma unroll
        for (int k = 0; k < 64; k++) s += w[k]*xb[lane + 32*k];
        #pragma unroll
        for (int o = 16; o; o >>= 1) s += __shfl_xor_sync(0xffffffffu, s, o);
        if (lane == 0){
            if (r < QLR) g_qa[b*QLR + r] = s + bias;
            else         g_kvpe[b*(KVLR+DR) + (r-QLR)] = s + bias;
        }
    }
}

// ========== K2: RMS-norm qa and kv; rope k_pe ==========
__global__ void k_norm_rope(const float* __restrict__ qnw, const float* __restrict__ kvnw,
                            const float* __restrict__ fcos, const float* __restrict__ fsin){
    int b = blockIdx.x, tid = threadIdx.x;
    __shared__ float red[16];
    __shared__ float sq, skv;
    float s = 0.f;
    for (int i = tid; i < QLR; i += 512){ float v = g_qa[b*QLR+i]; s += v*v; }
    #pragma unroll
    for (int o = 16; o; o >>= 1) s += __shfl_xor_sync(0xffffffffu, s, o);
    if ((tid&31) == 0) red[tid>>5] = s;
    __syncthreads();
    if (tid == 0){ float t=0; for (int i=0;i<16;i++) t += red[i];
                   sq = rsqrtf(t*(1.f/QLR) + 1e-6f); }
    __syncthreads();
    float s2 = 0.f;
    { float v = (tid < KVLR) ? g_kvpe[b*(KVLR+DR)+tid] : 0.f; s2 = v*v; }
    #pragma unroll
    for (int o = 16; o; o >>= 1) s2 += __shfl_xor_sync(0xffffffffu, s2, o);
    if ((tid&31) == 0) red[tid>>5] = s2;
    __syncthreads();
    if (tid == 0){ float t=0; for (int i=0;i<16;i++) t += red[i];
                   skv = rsqrtf(t*(1.f/KVLR) + 1e-6f); }
    __syncthreads();
    for (int i = tid; i < QLR; i += 512) g_qan[b*QLR+i] = g_qa[b*QLR+i]*qnw[i]*sq;
    if (tid < KVLR) g_kvn[b*KVLR+tid] = g_kvpe[b*(KVLR+DR)+tid]*kvnw[tid]*skv;
    if (tid < DR){
        int i = tid >> 1;
        float xr = g_kvpe[b*(KVLR+DR)+KVLR+2*i];
        float xi = g_kvpe[b*(KVLR+DR)+KVLR+2*i+1];
        float c = fcos[i], sn = fsin[i];
        g_pen[b*DR+tid] = (tid&1) ? (xr*sn + xi*c) : (xr*c - xi*sn);
    }
}

// ========== K3: q = qa_n @ wq_b^T + b ==========
__global__ void k_proj_qb(const float* __restrict__ wqb, const float* __restrict__ bqb){
    extern __shared__ float qs[];
    int tid = threadIdx.x;
    for (int i = tid; i < B*QLR; i += blockDim.x) qs[i] = g_qan[i];
    __syncthreads();
    int warp = tid >> 5, lane = tid & 31;
    int r = blockIdx.x * 8 + warp;
    const float* wr = wqb + (long)r*QLR;
    float w[48];
    #pragma unroll
    for (int k = 0; k < 48; k++) w[k] = wr[lane + 32*k];
    float bias = bqb[r];
    for (int b = 0; b < B; b++){
        const float* xb = qs + b*QLR;
        float s = 0.f;
        #pragma unroll
        for (int k = 0; k < 48; k++) s += w[k]*xb[lane + 32*k];
        #pragma unroll
        for (int o = 16; o; o >>= 1) s += __shfl_xor_sync(0xffffffffu, s, o);
        if (lane == 0) g_q[b*(H*(DN+DR)) + r] = s + bias;
    }
}

// ========== K4: q_full = [q_nope @ wkv_b[:, :DN], rope(q_pe)] ==========
// grid (H, 9), 512 threads. parts 0-7: 64-col slice; 8 d-groups of 16.
__global__ void k_qfull(const float* __restrict__ wkvb,
                        const float* __restrict__ fcos, const float* __restrict__ fsin){
    int h = blockIdx.x, part = blockIdx.y, tid = threadIdx.x;
    if (part < 8){
        __shared__ float qn[B][DN];
        __shared__ float red[8][B][65];
        for (int i = tid; i < B*DN; i += 512){ int b = i>>7, d = i&127;
            qn[b][d] = g_q[b*(H*(DN+DR)) + h*(DN+DR) + d]; }
        __syncthreads();
        int dg = tid >> 6, cc = tid & 63;
        int c = part*64 + cc;
        float acc[B];
        #pragma unroll
        for (int b = 0; b < B; b++) acc[b] = 0.f;
        const float* wp = wkvb + (long)(h*(DN+DV) + dg*16)*KVLR + c;
        #pragma unroll
        for (int ds = 0; ds < 16; ds += 4){
            float w0 = wp[(long)(ds+0)*KVLR];
            float w1 = wp[(long)(ds+1)*KVLR];
            float w2 = wp[(long)(ds+2)*KVLR];
            float w3 = wp[(long)(ds+3)*KVLR];
            #pragma unroll
            for (int b = 0; b < B; b++){
                float4 q = *(const float4*)(&qn[b][dg*16 + ds]);
                acc[b] += q.x*w0 + q.y*w1 + q.z*w2 + q.w*w3;
            }
        }
        #pragma unroll
        for (int b = 0; b < B; b++) red[dg][b][cc] = acc[b];
        __syncthreads();
        for (int i = tid; i < B*64; i += 512){
            int b = i >> 6, c2 = i & 63;
            float s = 0.f;
            #pragma unroll
            for (int d = 0; d < 8; d++) s += red[d][b][c2];
            g_qfull[(b*H + h)*DHEAD + part*64 + c2] = s;
        }
    } else {
        if (tid < DR){
            int i = tid >> 1;
            float c = fcos[i], sn = fsin[i];
            for (int b = 0; b < B; b++){
                float xr = g_q[b*(H*(DN+DR)) + h*(DN+DR) + DN + 2*i];
                float xi = g_q[b*(H*(DN+DR)) + h*(DN+DR) + DN + 2*i + 1];
                g_qfull[(b*H + h)*DHEAD + KVLR + tid] =
                    (tid&1) ? (xr*sn + xi*c) : (xr*c - xi*sn);
            }
        }
    }
}

// ========== K5: persistent split-K attention ==========
// grid (16, 8), 512 threads. Each CTA: 16 chunks x 32 tokens, online softmax,
// cp.async double-buffered kv, tf32 MMA for scores and P@KV.
// Q score-fragments hoisted to registers; 3 barriers per chunk.
#define SMF_KV0 0
#define SMF_KV1 18560
#define SMF_Q   37120
#define SMF_PR  46400
#define SMF_PS  48704
#define SMF_SC  49280
#define SM_TOTAL ((49280 + 16)*4)   // 197184 bytes

__device__ __forceinline__ void issue_chunk(
    const float* __restrict__ kvp, const float* __restrict__ pep,
    int b, int t0, uint32_t dstbase, const int* tk, const int* jk){
    #pragma unroll
    for (int k = 0; k < 9; k++){
        int tg = t0 + tk[k];
        int j = jk[k];
        const char* src;
        if (tg == T_PREFIX)
            src = (j < 128) ? (const char*)(g_kvn + b*KVLR) + j*16
                            : (const char*)(g_pen + b*DR) + (j-128)*16;
        else
            src = (j < 128) ? (const char*)(kvp + ((long)b*T_PREFIX + tg)*KVLR) + j*16
                            : (const char*)(pep + ((long)b*T_PREFIX + tg)*DR) + (j-128)*16;
        uint32_t dst = dstbase + (uint32_t)(tk[k]*2320 + j*16);
        asm volatile("cp.async.cg.shared.global [%0], [%1], 16;" :: "r"(dst), "l"(src));
    }
    asm volatile("cp.async.commit_group;" ::: "memory");
}

__global__ void __launch_bounds__(512, 1) k_attn(const float* __restrict__ kvp,
                                                 const float* __restrict__ pep){
    extern __shared__ float smf[];
    float* qs  = smf + SMF_Q;
    float* pr  = smf + SMF_PR;    // [4][16][36]
    float* ps  = smf + SMF_PS;    // [16][36]
    float* s_c = smf + SMF_SC;    // [16]
    int g = blockIdx.x, b = blockIdx.y, tid = threadIdx.x;
    int warp = tid >> 5, lane = tid & 31;
    int l4 = lane >> 2, lm4 = lane & 3;
    uint32_t sb = smem_u32(smf);

    int tk[9], jk[9];
    #pragma unroll
    for (int k = 0; k < 9; k++){ int idx = tid + 512*k; tk[k] = idx/144; jk[k] = idx%144; }

    // kick off chunk 0
    issue_chunk(kvp, pep, b, g*NCPC*CHUNK, sb + SMF_KV0*4, tk, jk);

    // load Q (warp h -> head h) while chunk 0 streams
    {
        int h = warp;
        const float* qr = g_qfull + (long)(b*H + h)*DHEAD;
        #pragma unroll
        for (int i = 0; i < 5; i++){
            int j = lane + 32*i;
            if (j < 144)
                *(float4*)(qs + h*KSTR + 4*j) = *(const float4*)(qr + 4*j);
        }
    }
    __syncthreads();

    // hoist Q tf32 fragments (loop-invariant): 18 kc steps x 2
    int tile_m = warp & 1, tile_n = (warp >> 1) & 1, kh = warp >> 2;
    uint32_t qf0[18], qf1[18];
    {
        const float* brow = qs + (tile_n*8 + l4)*KSTR + lm4;
        #pragma unroll
        for (int kc = 0; kc < 18; kc++){
            int k0 = kh*144 + kc*8;
            qf0[kc] = tf32_of(brow[k0]);
            qf1[kc] = tf32_of(brow[k0+4]);
        }
    }

    float m_run = -1e30f, l_run = 0.f;
    float acc[4][4];
    #pragma unroll
    for (int nt = 0; nt < 4; nt++)
        #pragma unroll
        for (int j = 0; j < 4; j++) acc[nt][j] = 0.f;

    for (int i = 0; i < NCPC; i++){
        if (i + 1 < NCPC){
            issue_chunk(kvp, pep, b, (g*NCPC + i + 1)*CHUNK,
                        sb + (((i+1)&1) ? SMF_KV1 : SMF_KV0)*4, tk, jk);
            asm volatile("cp.async.wait_group 1;" ::: "memory");
        } else {
            asm volatile("cp.async.wait_group 0;" ::: "memory");
        }
        __syncthreads();                        // (A) copy visible; prev accumulate done
        const float* kvs = smf + ((i&1) ? SMF_KV1 : SMF_KV0);

        // ---- scores: 2m x 2n x 4k-split; Q frags in registers ----
        {
            const float* arow0 = kvs + (tile_m*16 + l4)*KSTR + lm4;
            const float* arow1 = arow0 + 8*KSTR;
            float d0 = 0.f, d1 = 0.f, d2 = 0.f, d3 = 0.f;
            #pragma unroll
            for (int kc = 0; kc < 18; kc++){
                int k0 = kh*144 + kc*8;
                uint32_t a0 = tf32_of(arow0[k0]);
                uint32_t a1 = tf32_of(arow1[k0]);
                uint32_t a2 = tf32_of(arow0[k0+4]);
                uint32_t a3 = tf32_of(arow1[k0+4]);
                asm volatile("mma.sync.aligned.m16n8k8.row.col.f32.tf32.tf32.f32 "
                    "{%0,%1,%2,%3}, {%4,%5,%6,%7}, {%8,%9}, {%0,%1,%2,%3};"
                    : "+f"(d0),"+f"(d1),"+f"(d2),"+f"(d3)
                    : "r"(a0),"r"(a1),"r"(a2),"r"(a3), "r"(qf0[kc]),"r"(qf1[kc]));
            }
            int r0 = tile_m*16 + l4;
            int h0 = tile_n*8 + 2*lm4;
            pr[kh*576 + h0*PSTR + r0]           = d0;
            pr[kh*576 + (h0+1)*PSTR + r0]       = d1;
            pr[kh*576 + h0*PSTR + r0 + 8]       = d2;
            pr[kh*576 + (h0+1)*PSTR + r0 + 8]   = d3;
        }
        __syncthreads();                        // (B)

        // ---- online softmax: warp h, one token per lane ----
        {
            int h = warp;
            float v = (pr[h*PSTR + lane] + pr[576 + h*PSTR + lane]
                     + pr[1152 + h*PSTR + lane] + pr[1728 + h*PSTR + lane]) * SCALEF;
            float bm = v;
            #pragma unroll
            for (int o = 16; o; o >>= 1) bm = fmaxf(bm, __shfl_xor_sync(0xffffffffu, bm, o));
            float mn = fmaxf(m_run, bm);
            float corr = __expf(m_run - mn);
            float p = __expf(v - mn);
            float l = p;
            #pragma unroll
            for (int o = 16; o; o >>= 1) l += __shfl_xor_sync(0xffffffffu, l, o);
            l_run = l_run*corr + l;
            m_run = mn;
            ps[h*PSTR + lane] = p;
            if (lane == 0) s_c[h] = corr;
        }
        __syncthreads();                        // (C)

        // ---- accumulate via tf32 MMA: out[16h][32c per warp] += P @ KV ----
        {
            int n0 = warp*32;
            float corr0 = s_c[l4], corr1 = s_c[l4+8];
            #pragma unroll
            for (int nt = 0; nt < 4; nt++){
                acc[nt][0] *= corr0; acc[nt][1] *= corr0;
                acc[nt][2] *= corr1; acc[nt][3] *= corr1;
            }
            #pragma unroll
            for (int ks = 0; ks < 4; ks++){
                int k0 = ks*8;
                uint32_t a0 = tf32_of(ps[l4*PSTR + k0 + lm4]);
                uint32_t a1 = tf32_of(ps[(l4+8)*PSTR + k0 + lm4]);
                uint32_t a2 = tf32_of(ps[l4*PSTR + k0 + 4 + lm4]);
                uint32_t a3 = tf32_of(ps[(l4+8)*PSTR + k0 + 4 + lm4]);
                #pragma unroll
                for (int nt = 0; nt < 4; nt++){
                    int cn = n0 + nt*8 + l4;
                    uint32_t b0 = tf32_of(kvs[(k0 + lm4)*KSTR + cn]);
                    uint32_t b1 = tf32_of(kvs[(k0 + 4 + lm4)*KSTR + cn]);
                    asm volatile("mma.sync.aligned.m16n8k8.row.col.f32.tf32.tf32.f32 "
                        "{%0,%1,%2,%3}, {%4,%5,%6,%7}, {%8,%9}, {%0,%1,%2,%3};"
                        : "+f"(acc[nt][0]),"+f"(acc[nt][1]),"+f"(acc[nt][2]),"+f"(acc[nt][3])
                        : "r"(a0),"r"(a1),"r"(a2),"r"(a3), "r"(b0),"r"(b1));
                }
            }
        }
        // no end barrier: next issue targets the buffer accumulated 2 chunks ago,
        // ordered by barrier (A) of the next iteration.
    }

    if (lane == 0){
        g_pm[(b*NCHUNK + g)*H + warp] = m_run;
        g_pl[(b*NCHUNK + g)*H + warp] = l_run;
    }
    {
        int n0 = warp*32;
        long base0 = ((long)(b*NCHUNK + g)*H + l4)*KVLR;
        long base1 = ((long)(b*NCHUNK + g)*H + l4 + 8)*KVLR;
        #pragma unroll
        for (int nt = 0; nt < 4; nt++){
            int c = n0 + nt*8 + 2*lm4;
            *(float2*)(g_pout + base0 + c) = make_float2(acc[nt][0], acc[nt][1]);
            *(float2*)(g_pout + base1 + c) = make_float2(acc[nt][2], acc[nt][3]);
        }
    }
}

// ========== K6: combine split-softmax partials + V projection ==========
__global__ void k_reduce(const float* __restrict__ wkvb){
    int h = blockIdx.x, b = blockIdx.y, tid = threadIdx.x;
    __shared__ float sm_m[NCHUNK], sm_l[NCHUNK], wk[NCHUNK];
    __shared__ float so[KVLR];
    if (tid < NCHUNK){
        sm_m[tid] = g_pm[(b*NCHUNK + tid)*H + h];
        sm_l[tid] = g_pl[(b*NCHUNK + tid)*H + h];
    }
    __syncthreads();
    if (tid < 32){
        float mv = (tid < NCHUNK) ? sm_m[tid] : -1e30f;
        float M = mv;
        #pragma unroll
        for (int o = 16; o; o >>= 1) M = fmaxf(M, __shfl_xor_sync(0xffffffffu, M, o));
        float e = __expf(mv - M);
        float L = (tid < NCHUNK) ? e*sm_l[tid] : 0.f;
        #pragma unroll
        for (int o = 16; o; o >>= 1) L += __shfl_xor_sync(0xffffffffu, L, o);
        if (tid < NCHUNK) wk[tid] = e / L;
    }
    __syncthreads();
    float out = 0.f;
    #pragma unroll
    for (int k = 0; k < NCHUNK; k++)
        out += wk[k]*g_pout[((long)(b*NCHUNK + k)*H + h)*KVLR + tid];
    so[tid] = out;
    __syncthreads();
    int d = tid >> 2, part = tid & 3;
    const float* wr = wkvb + (long)(h*(DN+DV) + DN + d)*KVLR + part*128;
    const float* sp = so + part*128;
    float s = 0.f;
    #pragma unroll 8
    for (int c = 0; c < 128; c++) s += sp[c]*wr[c];
    s += __shfl_xor_sync(0xffffffffu, s, 1);
    s += __shfl_xor_sync(0xffffffffu, s, 2);
    if (part == 0) g_out2[(b*H + h)*DV + d] = s;
}

// ========== K7: y = out2 @ wo^T + wo_b ==========
__global__ void k_proj_o(const float* __restrict__ wo, const float* __restrict__ wob,
                         float* __restrict__ out){
    extern __shared__ float xs[];
    int tid = threadIdx.x;
    for (int i = tid; i < B*DIM; i += blockDim.x) xs[i] = g_out2[i];
    __syncthreads();
    int warp = tid >> 5, lane = tid & 31;
    int j = blockIdx.x * 8 + warp;
    const float* wr = wo + (long)j*DIM;
    float w[64];
    #pragma unroll
    for (int k = 0; k < 64; k++) w[k] = wr[lane + 32*k];
    float bias = wob[j];
    for (int b = 0; b < B; b++){
        const float* xb = xs + b*DIM;
        float s = 0.f;
        #pragma unroll
        for (int k = 0; k < 64; k++) s += w[k]*xb[lane + 32*k];
        #pragma unroll
        for (int o = 16; o; o >>= 1) s += __shfl_xor_sync(0xffffffffu, s, o);
        if (lane == 0) out[b*DIM + j] = s + bias;
    }
}

// ---------------- host launcher ----------------
extern "C" void kernel_launch(void* const* d_in, const int* in_sizes, int n_in,
                              void* d_out, int out_size){
    const float* x    = (const float*)d_in[0];
    const float* fcos = (const float*)d_in[2];
    const float* fsin = (const float*)d_in[3];
    const float* kvp  = (const float*)d_in[4];
    const float* pep  = (const float*)d_in[5];
    const float* wqa  = (const float*)d_in[6];
    const float* bqa  = (const float*)d_in[7];
    const float* qnw  = (const float*)d_in[8];
    const float* wqb  = (const float*)d_in[9];
    const float* bqb  = (const float*)d_in[10];
    const float* wkva = (const float*)d_in[11];
    const float* bkva = (const float*)d_in[12];
    const float* kvnw = (const float*)d_in[13];
    const float* wkvb = (const float*)d_in[14];
    const float* wo   = (const float*)d_in[15];
    const float* wob  = (const float*)d_in[16];
    float* out = (float*)d_out;

    const int SMEM_K1 = B*DIM*4;
    const int SMEM_K3 = B*QLR*4;
    const int SMEM_K7 = B*DIM*4;
    cudaFuncSetAttribute(k_proj_a,  cudaFuncAttributeMaxDynamicSharedMemorySize, SMEM_K1);
    cudaFuncSetAttribute(k_proj_qb, cudaFuncAttributeMaxDynamicSharedMemorySize, SMEM_K3);
    cudaFuncSetAttribute(k_attn,    cudaFuncAttributeMaxDynamicSharedMemorySize, SM_TOTAL);
    cudaFuncSetAttribute(k_proj_o,  cudaFuncAttributeMaxDynamicSharedMemorySize, SMEM_K7);

    k_proj_a<<<(QLR+KVLR+DR)/8, 256, SMEM_K1>>>(x, wqa, bqa, wkva, bkva);
    k_norm_rope<<<B, 512>>>(qnw, kvnw, fcos, fsin);
    k_proj_qb<<<(H*(DN+DR))/8, 256, SMEM_K3>>>(wqb, bqb);
    { dim3 g(H, 9); k_qfull<<<g, 512>>>(wkvb, fcos, fsin); }
    { dim3 g(NCHUNK, B); k_attn<<<g, 512, SM_TOTAL>>>(kvp, pep); }
    { dim3 g(H, B); k_reduce<<<g, 512>>>(wkvb); }
    k_proj_o<<<DIM/8, 256, SMEM_K7>>>(wo, wob, out);
}